// round 3
// baseline (speedup 1.0000x reference)
#include <cuda_runtime.h>

#define NN   50000
#define NE   640000
#define HID  128
#define NG   20
#define EF   4
#define ZDIM (2*HID + NG + EF)   // 280
#define TE   32
#define NT   32
#define XOUT_OFF (NN*HID)

// scratch (allocation-free rule: __device__ globals)
__device__ __align__(16) float g_mi[NN*HID];
__device__ __align__(16) float g_dx[NN*3];

__device__ __forceinline__ float sigmoidf_(float v){ return 1.f/(1.f+__expf(-v)); }
__device__ __forceinline__ float siluf_(float v){ return v/(1.f+__expf(-v)); }

__device__ __forceinline__ void red_add_v4(float* a, float x, float y, float z, float w){
    asm volatile("red.global.add.v4.f32 [%0], {%1,%2,%3,%4};"
                 :: "l"(a), "f"(x), "f"(y), "f"(z), "f"(w) : "memory");
}

__device__ __forceinline__ int clampi(int v){ return v < 0 ? 0 : (v >= NN ? NN-1 : v); }

__device__ __forceinline__ void zero_acc(float acc[2][8]){
    #pragma unroll
    for (int r=0;r<2;r++)
        #pragma unroll
        for (int j=0;j<8;j++) acc[r][j]=0.f;
}

// Register-tiled GEMM: C[32][128] += S[K][32] (smem, ld 33) * W[K][128] (global, staged in ws)
// Thread (tx,ty): rows r0=2*ty..+1, cols c0=8*tx..+7
template<int K, int KC>
__device__ __forceinline__ void gemm_tile(const float* __restrict__ src,
                                          const float* __restrict__ Wg,
                                          float* ws, int t, int r0, int c0,
                                          float acc[2][8])
{
    for (int kb = 0; kb < K; kb += KC) {
        __syncthreads();
        for (int i = t; i < KC*128; i += 256)
            ws[i] = Wg[(kb + (i >> 7))*128 + (i & 127)];
        __syncthreads();
        #pragma unroll 4
        for (int kk = 0; kk < KC; ++kk) {
            float a0 = src[(kb+kk)*33 + r0];
            float a1 = src[(kb+kk)*33 + r0 + 1];
            const float4* wr = (const float4*)(ws + kk*128 + c0);
            float4 w0 = wr[0], w1 = wr[1];
            acc[0][0]+=a0*w0.x; acc[0][1]+=a0*w0.y; acc[0][2]+=a0*w0.z; acc[0][3]+=a0*w0.w;
            acc[0][4]+=a0*w1.x; acc[0][5]+=a0*w1.y; acc[0][6]+=a0*w1.z; acc[0][7]+=a0*w1.w;
            acc[1][0]+=a1*w0.x; acc[1][1]+=a1*w0.y; acc[1][2]+=a1*w0.z; acc[1][3]+=a1*w0.w;
            acc[1][4]+=a1*w1.x; acc[1][5]+=a1*w1.y; acc[1][6]+=a1*w1.z; acc[1][7]+=a1*w1.w;
        }
    }
}

__global__ void zero_kernel() {
    int i = blockIdx.x*256 + threadIdx.x;
    if (i < NN*HID/4) ((float4*)g_mi)[i] = make_float4(0.f,0.f,0.f,0.f);
    if (i < NN*3/4)   ((float4*)g_dx)[i] = make_float4(0.f,0.f,0.f,0.f);
}

// dyn smem: zs[280][33] | ws[40][128] | t1s[128][33] | mjs[128][33]
#define EDGE_SMEM ((280*33 + 40*128 + 128*33 + 128*33)*4)

__global__ __launch_bounds__(256) void edge_kernel(
    const float* __restrict__ h, const float* __restrict__ x,
    const int* __restrict__ eidx, const float* __restrict__ edge_attr,
    const float* __restrict__ We1, const float* __restrict__ be1,
    const float* __restrict__ We2, const float* __restrict__ be2,
    const float* __restrict__ Winf, const float* __restrict__ binf,
    const float* __restrict__ Wx1, const float* __restrict__ bx1,
    const float* __restrict__ Wx2)
{
    extern __shared__ float sm[];
    float* zs  = sm;                     // [280][33]
    float* ws  = sm + 280*33;            // [40][128]
    float* t1s = ws + 40*128;            // [128][33]
    float* mjs = t1s + 128*33;           // [128][33]
    __shared__ int   dstl[TE], srcl[TE];
    __shared__ float rels[3][TE], ds[TE];

    const int t  = threadIdx.x;
    const int tx = t & 15, ty = t >> 4;
    const int r0 = 2*ty, c0 = 8*tx;
    const int e0 = blockIdx.x * TE;

    if (t < TE) {
        int s = clampi(eidx[e0 + t]);
        int d = clampi(eidx[NE + e0 + t]);
        srcl[t] = s; dstl[t] = d;
        float d0 = x[d*3+0]-x[s*3+0];
        float d1 = x[d*3+1]-x[s*3+1];
        float d2 = x[d*3+2]-x[s*3+2];
        rels[0][t]=d0; rels[1][t]=d1; rels[2][t]=d2;
        ds[t] = sqrtf(d0*d0 + d1*d1 + d2*d2 + 1e-8f);
    }
    __syncthreads();

    // build z tile: [h[dst] | h[src] | gauss(d) | edge_attr]
    for (int i = t; i < TE*HID; i += 256) {
        int e = i >> 7, k = i & 127;
        zs[k*33 + e]         = h[dstl[e]*HID + k];
        zs[(HID+k)*33 + e]   = h[srcl[e]*HID + k];
    }
    const float step  = 10.f/19.f;
    const float coeff = -0.5f/(step*step);
    for (int i = t; i < TE*NG; i += 256) {
        int e = i/NG, g = i - e*NG;
        float dd = ds[e] - step*(float)g;
        zs[(2*HID+g)*33 + e] = __expf(coeff*dd*dd);
    }
    for (int i = t; i < TE*EF; i += 256) {
        int e = i >> 2, a = i & 3;
        zs[(2*HID+NG+a)*33 + e] = edge_attr[(size_t)(e0+e)*EF + a];
    }

    // GEMM1: t1 = silu(z @ We1 + be1)
    float acc[2][8];
    zero_acc(acc);
    gemm_tile<ZDIM,40>(zs, We1, ws, t, r0, c0, acc);
    #pragma unroll
    for (int r=0;r<2;r++) {
        #pragma unroll
        for (int j=0;j<8;j++)
            t1s[(c0+j)*33 + r0 + r] = siluf_(acc[r][j] + be1[c0+j]);
    }

    // GEMM2: mij = silu(t1 @ We2 + be2)
    float acc2[2][8];
    zero_acc(acc2);
    gemm_tile<HID,32>(t1s, We2, ws, t, r0, c0, acc2);
    float mreg[2][8];
    #pragma unroll
    for (int r=0;r<2;r++) {
        #pragma unroll
        for (int j=0;j<8;j++)
            mreg[r][j] = siluf_(acc2[r][j] + be2[c0+j]);
    }

    // eij = sigmoid(mij . Winf + binf)  (reduce over 16-lane column groups)
    float p0 = 0.f, p1 = 0.f;
    #pragma unroll
    for (int j=0;j<8;j++) {
        float w = Winf[c0+j];
        p0 += mreg[0][j]*w; p1 += mreg[1][j]*w;
    }
    #pragma unroll
    for (int off=8; off; off >>= 1) {
        p0 += __shfl_xor_sync(0xffffffffu, p0, off);
        p1 += __shfl_xor_sync(0xffffffffu, p1, off);
    }
    float bi = binf[0];
    float eg0 = sigmoidf_(p0 + bi), eg1 = sigmoidf_(p1 + bi);

    // scatter mi += mij * eij (vector red), stash mij for GEMM3
    {
        int d0 = dstl[r0], d1 = dstl[r0+1];
        red_add_v4(&g_mi[d0*HID + c0],     mreg[0][0]*eg0, mreg[0][1]*eg0, mreg[0][2]*eg0, mreg[0][3]*eg0);
        red_add_v4(&g_mi[d0*HID + c0 + 4], mreg[0][4]*eg0, mreg[0][5]*eg0, mreg[0][6]*eg0, mreg[0][7]*eg0);
        red_add_v4(&g_mi[d1*HID + c0],     mreg[1][0]*eg1, mreg[1][1]*eg1, mreg[1][2]*eg1, mreg[1][3]*eg1);
        red_add_v4(&g_mi[d1*HID + c0 + 4], mreg[1][4]*eg1, mreg[1][5]*eg1, mreg[1][6]*eg1, mreg[1][7]*eg1);
        #pragma unroll
        for (int j=0;j<8;j++) {
            mjs[(c0+j)*33 + r0]     = mreg[0][j];
            mjs[(c0+j)*33 + r0 + 1] = mreg[1][j];
        }
    }

    // GEMM3: xg = tanh(silu(mij @ Wx1 + bx1) . Wx2)
    float acc3[2][8];
    zero_acc(acc3);
    gemm_tile<HID,32>(mjs, Wx1, ws, t, r0, c0, acc3);
    float q0 = 0.f, q1 = 0.f;
    #pragma unroll
    for (int j=0;j<8;j++) {
        float b  = bx1[c0+j];
        float w  = Wx2[c0+j];
        q0 += siluf_(acc3[0][j] + b) * w;
        q1 += siluf_(acc3[1][j] + b) * w;
    }
    #pragma unroll
    for (int off=8; off; off >>= 1) {
        q0 += __shfl_xor_sync(0xffffffffu, q0, off);
        q1 += __shfl_xor_sync(0xffffffffu, q1, off);
    }
    float s0 = tanhf(q0) / (ds[r0]   + 1.f);
    float s1 = tanhf(q1) / (ds[r0+1] + 1.f);
    if (tx < 3) {
        atomicAdd(&g_dx[dstl[r0]*3   + tx], rels[tx][r0]   * s0);
        atomicAdd(&g_dx[dstl[r0+1]*3 + tx], rels[tx][r0+1] * s1);
    }
}

// dyn smem: zs[256][33] | ws[32][128] | t1s[128][33]
#define NODE_SMEM ((256*33 + 32*128 + 128*33)*4)

__global__ __launch_bounds__(256) void node_kernel(
    const float* __restrict__ h, const float* __restrict__ x,
    const float* __restrict__ mask,
    const float* __restrict__ Wn1, const float* __restrict__ bn1,
    const float* __restrict__ Wn2, const float* __restrict__ bn2,
    float* __restrict__ out)
{
    extern __shared__ float sm[];
    float* zs  = sm;                 // [256][33]
    float* ws  = sm + 256*33;        // [32][128]
    float* t1s = ws + 32*128;        // [128][33]

    const int t  = threadIdx.x;
    const int tx = t & 15, ty = t >> 4;
    const int r0 = 2*ty, c0 = 8*tx;
    const int n0 = blockIdx.x * NT;

    for (int i = t; i < NT*HID; i += 256) {
        int e = i >> 7, k = i & 127;
        int node = n0 + e;
        float mi_ = 0.f, hh = 0.f;
        if (node < NN) { mi_ = g_mi[node*HID + k]; hh = h[node*HID + k]; }
        zs[k*33 + e]        = mi_;
        zs[(HID+k)*33 + e]  = hh;
    }

    float acc[2][8];
    zero_acc(acc);
    gemm_tile<2*HID,32>(zs, Wn1, ws, t, r0, c0, acc);
    #pragma unroll
    for (int r=0;r<2;r++) {
        #pragma unroll
        for (int j=0;j<8;j++)
            t1s[(c0+j)*33 + r0 + r] = siluf_(acc[r][j] + bn1[c0+j]);
    }

    float acc2[2][8];
    zero_acc(acc2);
    gemm_tile<HID,32>(t1s, Wn2, ws, t, r0, c0, acc2);

    #pragma unroll
    for (int r=0;r<2;r++) {
        int node = n0 + r0 + r;
        if (node < NN) {
            #pragma unroll
            for (int j=0;j<8;j++)
                out[node*HID + c0 + j] = h[node*HID + c0 + j] + acc2[r][j] + bn2[c0+j];
        }
    }
    if (t < NT*3) {
        int e = t/3, a = t - 3*e;
        int node = n0 + e;
        if (node < NN)
            out[XOUT_OFF + node*3 + a] = x[node*3 + a] + g_dx[node*3 + a]*mask[node];
    }
}

extern "C" void kernel_launch(void* const* d_in, const int* in_sizes, int n_in,
                              void* d_out, int out_size)
{
    const float* h         = (const float*)d_in[0];
    const float* x         = (const float*)d_in[1];
    const int*   eidx      = (const int*)d_in[2];   // jnp.int64 downgrades to int32 (x64 disabled)
    const float* mask      = (const float*)d_in[3];
    const float* edge_attr = (const float*)d_in[4];
    const float* We1  = (const float*)d_in[5];
    const float* be1  = (const float*)d_in[6];
    const float* We2  = (const float*)d_in[7];
    const float* be2  = (const float*)d_in[8];
    const float* Winf = (const float*)d_in[9];
    const float* binf = (const float*)d_in[10];
    const float* Wx1  = (const float*)d_in[11];
    const float* bx1  = (const float*)d_in[12];
    const float* Wx2  = (const float*)d_in[13];
    const float* Wn1  = (const float*)d_in[14];
    const float* bn1  = (const float*)d_in[15];
    const float* Wn2  = (const float*)d_in[16];
    const float* bn2  = (const float*)d_in[17];
    float* out = (float*)d_out;

    cudaFuncSetAttribute(edge_kernel, cudaFuncAttributeMaxDynamicSharedMemorySize, EDGE_SMEM);
    cudaFuncSetAttribute(node_kernel, cudaFuncAttributeMaxDynamicSharedMemorySize, NODE_SMEM);

    zero_kernel<<<(NN*HID/4 + 255)/256, 256>>>();
    edge_kernel<<<NE/TE, 256, EDGE_SMEM>>>(h, x, eidx, edge_attr,
                                           We1, be1, We2, be2, Winf, binf,
                                           Wx1, bx1, Wx2);
    node_kernel<<<(NN + NT - 1)/NT, 256, NODE_SMEM>>>(h, x, mask,
                                                      Wn1, bn1, Wn2, bn2, out);
}

// round 4
// speedup vs baseline: 3.3535x; 3.3535x over previous
#include <cuda_runtime.h>

#define NN   50000
#define NE   640000
#define HID  128
#define NG   20
#define EF   4
#define XOUT_OFF (NN*HID)
#define LDA  68     // floats per K-row slab (64 rows + 4 pad), 16B aligned
#define LDA4 17     // float4 units per slab

// scratch (allocation-free rule: __device__ globals)
__device__ __align__(16) float g_mi[NN*HID];
__device__ __align__(16) float g_p [NN*HID];   // h @ We1[0:128]    (dst part)
__device__ __align__(16) float g_q [NN*HID];   // h @ We1[128:256]  (src part)
__device__ __align__(16) float g_dx[NN*3];

__device__ __forceinline__ float sigmoidf_(float v){ return 1.f/(1.f+__expf(-v)); }
__device__ __forceinline__ float siluf_(float v){ return v/(1.f+__expf(-v)); }
__device__ __forceinline__ int clampi(int v){ return v < 0 ? 0 : (v >= NN ? NN-1 : v); }
__device__ __forceinline__ float4 ld4(const float* p){ return *(const float4*)p; }

__device__ __forceinline__ void red_add_v4(float* a, float x, float y, float z, float w){
    asm volatile("red.global.add.v4.f32 [%0], {%1,%2,%3,%4};"
                 :: "l"(a), "f"(x), "f"(y), "f"(z), "f"(w) : "memory");
}

__device__ __forceinline__ void zero_acc(float acc[4][8]){
    #pragma unroll
    for (int r=0;r<4;r++)
        #pragma unroll
        for (int j=0;j<8;j++) acc[r][j]=0.f;
}

// swizzled transposed store: column c of next GEMM, 4 rows starting at 4*ty
__device__ __forceinline__ void st_col4(float* buf, int c, int ty, float4 v){
    ((float4*)buf)[c*LDA4 + (ty ^ ((c>>3)&15))] = v;
}

// C[64][128] += S[K][64-slab] * W[K][128]. Thread (tx,ty): rows 4*ty.., cols 8*tx..
// SWZ: source stored with xor-swizzled float4 rows (epilogue-transposed buffers).
template<int K, int KC, bool SWZ>
__device__ __forceinline__ void gemm4(const float* __restrict__ src,
                                      const float* __restrict__ Wg,
                                      float* ws, int t, int ty, int c0,
                                      float acc[4][8])
{
    const float4* s4 = (const float4*)src;
    for (int kb = 0; kb < K; kb += KC) {
        __syncthreads();
        {
            const float4* Wg4 = (const float4*)(Wg + kb*128);
            float4* ws4 = (float4*)ws;
            for (int i = t; i < KC*32; i += 256) ws4[i] = Wg4[i];
        }
        __syncthreads();
        #pragma unroll 8
        for (int kk = 0; kk < KC; ++kk) {
            int k = kb + kk;
            float4 a = SWZ ? s4[k*LDA4 + (ty ^ ((k>>3)&15))]
                           : s4[k*LDA4 + ty];
            const float4* wr = (const float4*)(ws + kk*128 + c0);
            float4 w0 = wr[0], w1 = wr[1];
            float av[4] = {a.x,a.y,a.z,a.w};
            float wv[8] = {w0.x,w0.y,w0.z,w0.w,w1.x,w1.y,w1.z,w1.w};
            #pragma unroll
            for (int r=0;r<4;r++)
                #pragma unroll
                for (int j=0;j<8;j++) acc[r][j] += av[r]*wv[j];
        }
    }
}

__global__ void zero_kernel() {
    int i = blockIdx.x*256 + threadIdx.x;
    if (i < NN*HID/4) ((float4*)g_mi)[i] = make_float4(0.f,0.f,0.f,0.f);
    if (i < NN*3/4)   ((float4*)g_dx)[i] = make_float4(0.f,0.f,0.f,0.f);
}

// ---------------- node precompute: P = h@We1[0:128], Q = h@We1[128:256] -----
#define PRE_SMEM ((128*LDA + 64*128)*4)
__global__ __launch_bounds__(256,2) void pre_kernel(
    const float* __restrict__ h, const float* __restrict__ We1)
{
    extern __shared__ float sm[];
    float* hs = sm;              // [128][LDA]
    float* ws = sm + 128*LDA;    // [64][128]
    const int t = threadIdx.x;
    const int tx = t & 15, ty = t >> 4;
    const int c0 = 8*tx, r0 = 4*ty;
    const int n0 = blockIdx.x * 64;

    for (int i = t; i < 64*128; i += 256) {
        int e = i >> 7, k = i & 127;          // wait: want k fast for coalesced
        (void)e; (void)k;
    }
    // coalesced: consecutive t -> consecutive k within one node row
    for (int i = t; i < 64*128; i += 256) {
        int e = i >> 7;        // node within tile
        int k = i & 127;       // feature
        int node = n0 + e;
        hs[k*LDA + e] = (node < NN) ? h[node*HID + k] : 0.f;
    }

    float acc[4][8];
    zero_acc(acc);
    gemm4<128,64,false>(hs, We1, ws, t, ty, c0, acc);
    #pragma unroll
    for (int r=0;r<4;r++) {
        int node = n0 + r0 + r;
        if (node < NN) {
            *(float4*)(g_p + node*HID + c0)     = make_float4(acc[r][0],acc[r][1],acc[r][2],acc[r][3]);
            *(float4*)(g_p + node*HID + c0 + 4) = make_float4(acc[r][4],acc[r][5],acc[r][6],acc[r][7]);
        }
    }
    zero_acc(acc);
    gemm4<128,64,false>(hs, We1 + 128*128, ws, t, ty, c0, acc);
    #pragma unroll
    for (int r=0;r<4;r++) {
        int node = n0 + r0 + r;
        if (node < NN) {
            *(float4*)(g_q + node*HID + c0)     = make_float4(acc[r][0],acc[r][1],acc[r][2],acc[r][3]);
            *(float4*)(g_q + node*HID + c0 + 4) = make_float4(acc[r][4],acc[r][5],acc[r][6],acc[r][7]);
        }
    }
}

// ---------------- edge kernel ----------------
// dyn smem: fe[24][LDA] | ws[64][128] | t1s[128][LDA]  (t1s reused for mij)
#define EDGE_SMEM ((24*LDA + 64*128 + 128*LDA)*4)
__global__ __launch_bounds__(256,2) void edge_kernel(
    const float* __restrict__ x,
    const int* __restrict__ eidx, const float* __restrict__ edge_attr,
    const float* __restrict__ We1, const float* __restrict__ be1,
    const float* __restrict__ We2, const float* __restrict__ be2,
    const float* __restrict__ Winf, const float* __restrict__ binf,
    const float* __restrict__ Wx1, const float* __restrict__ bx1,
    const float* __restrict__ Wx2)
{
    extern __shared__ float sm[];
    float* fe  = sm;                    // [24][LDA]
    float* ws  = sm + 24*LDA;           // [64][128]
    float* t1s = ws + 64*128;           // [128][LDA] (swizzled f4 rows)
    __shared__ int   dstl[64], srcl[64];
    __shared__ float rels[3][64], ds_s[64];

    const int t  = threadIdx.x;
    const int tx = t & 15, ty = t >> 4;
    const int c0 = 8*tx, r0 = 4*ty;
    const long e0 = (long)blockIdx.x * 64;

    if (t < 64) {
        int s = clampi(eidx[e0 + t]);
        int d = clampi(eidx[NE + e0 + t]);
        srcl[t] = s; dstl[t] = d;
        float d0 = x[d*3+0]-x[s*3+0];
        float d1 = x[d*3+1]-x[s*3+1];
        float d2 = x[d*3+2]-x[s*3+2];
        rels[0][t]=d0; rels[1][t]=d1; rels[2][t]=d2;
        ds_s[t] = sqrtf(d0*d0 + d1*d1 + d2*d2 + 1e-8f);
    }
    __syncthreads();

    // feature tile: gauss(d) [20] | edge_attr [4]
    const float step  = 10.f/19.f;
    const float coeff = -0.5f/(step*step);
    for (int i = t; i < 64*24; i += 256) {
        int e = i / 24, k = i - e*24;
        float v;
        if (k < NG) { float dd = ds_s[e] - step*(float)k; v = __expf(coeff*dd*dd); }
        else        { v = edge_attr[(e0+e)*EF + (k-NG)]; }
        fe[k*LDA + e] = v;
    }

    // GEMM1 (K=24 remainder) + gathered P/Q + bias -> silu -> t1s
    float acc[4][8];
    zero_acc(acc);
    gemm4<24,24,false>(fe, We1 + 256*128, ws, t, ty, c0, acc);
    {
        float bv[8];
        #pragma unroll
        for (int j=0;j<8;j++) bv[j] = be1[c0+j];
        #pragma unroll
        for (int r=0;r<4;r++) {
            int dn = dstl[r0+r], sn = srcl[r0+r];
            float4 p0 = ld4(g_p + dn*HID + c0), p1 = ld4(g_p + dn*HID + c0 + 4);
            float4 q0 = ld4(g_q + sn*HID + c0), q1 = ld4(g_q + sn*HID + c0 + 4);
            acc[r][0] = siluf_(acc[r][0] + p0.x + q0.x + bv[0]);
            acc[r][1] = siluf_(acc[r][1] + p0.y + q0.y + bv[1]);
            acc[r][2] = siluf_(acc[r][2] + p0.z + q0.z + bv[2]);
            acc[r][3] = siluf_(acc[r][3] + p0.w + q0.w + bv[3]);
            acc[r][4] = siluf_(acc[r][4] + p1.x + q1.x + bv[4]);
            acc[r][5] = siluf_(acc[r][5] + p1.y + q1.y + bv[5]);
            acc[r][6] = siluf_(acc[r][6] + p1.z + q1.z + bv[6]);
            acc[r][7] = siluf_(acc[r][7] + p1.w + q1.w + bv[7]);
        }
        #pragma unroll
        for (int j=0;j<8;j++)
            st_col4(t1s, c0+j, ty, make_float4(acc[0][j],acc[1][j],acc[2][j],acc[3][j]));
    }

    // GEMM2: mij = silu(t1 @ We2 + be2)
    zero_acc(acc);
    gemm4<128,64,true>(t1s, We2, ws, t, ty, c0, acc);
    {
        #pragma unroll
        for (int r=0;r<4;r++)
            #pragma unroll
            for (int j=0;j<8;j++)
                acc[r][j] = siluf_(acc[r][j] + be2[c0+j]);
    }

    // eij = sigmoid(mij . Winf + binf), scatter mi += mij*eij
    {
        float p[4] = {0.f,0.f,0.f,0.f};
        #pragma unroll
        for (int j=0;j<8;j++) {
            float w = Winf[c0+j];
            #pragma unroll
            for (int r=0;r<4;r++) p[r] += acc[r][j]*w;
        }
        #pragma unroll
        for (int off=8; off; off >>= 1)
            #pragma unroll
            for (int r=0;r<4;r++) p[r] += __shfl_xor_sync(0xffffffffu, p[r], off);
        float bi = binf[0];
        #pragma unroll
        for (int r=0;r<4;r++) {
            float eg = sigmoidf_(p[r] + bi);
            int dn = dstl[r0+r];
            red_add_v4(&g_mi[dn*HID + c0],
                       acc[r][0]*eg, acc[r][1]*eg, acc[r][2]*eg, acc[r][3]*eg);
            red_add_v4(&g_mi[dn*HID + c0 + 4],
                       acc[r][4]*eg, acc[r][5]*eg, acc[r][6]*eg, acc[r][7]*eg);
        }
    }

    // overwrite t1s with mij (all threads done reading t1s after barrier)
    __syncthreads();
    #pragma unroll
    for (int j=0;j<8;j++)
        st_col4(t1s, c0+j, ty, make_float4(acc[0][j],acc[1][j],acc[2][j],acc[3][j]));

    // GEMM3: xg = tanh(silu(mij @ Wx1 + bx1) . Wx2); coordinate scatter
    zero_acc(acc);
    gemm4<128,64,true>(t1s, Wx1, ws, t, ty, c0, acc);
    {
        float q[4] = {0.f,0.f,0.f,0.f};
        #pragma unroll
        for (int j=0;j<8;j++) {
            float b = bx1[c0+j];
            float w = Wx2[c0+j];
            #pragma unroll
            for (int r=0;r<4;r++) q[r] += siluf_(acc[r][j] + b)*w;
        }
        #pragma unroll
        for (int off=8; off; off >>= 1)
            #pragma unroll
            for (int r=0;r<4;r++) q[r] += __shfl_xor_sync(0xffffffffu, q[r], off);
        if (tx < 3) {
            #pragma unroll
            for (int r=0;r<4;r++) {
                float s = tanhf(q[r]) / (ds_s[r0+r] + 1.f);
                atomicAdd(&g_dx[dstl[r0+r]*3 + tx], rels[tx][r0+r]*s);
            }
        }
    }
}

// ---------------- node kernel ----------------
// dyn smem: zs[256][LDA] | ws[64][128]    (t1 reuses zs rows 0..127, swizzled)
#define NODE_SMEM ((256*LDA + 64*128)*4)
__global__ __launch_bounds__(256,2) void node_kernel(
    const float* __restrict__ h, const float* __restrict__ x,
    const float* __restrict__ mask,
    const float* __restrict__ Wn1, const float* __restrict__ bn1,
    const float* __restrict__ Wn2, const float* __restrict__ bn2,
    float* __restrict__ out)
{
    extern __shared__ float sm[];
    float* zs = sm;               // [256][LDA]
    float* ws = sm + 256*LDA;     // [64][128]

    const int t  = threadIdx.x;
    const int tx = t & 15, ty = t >> 4;
    const int c0 = 8*tx, r0 = 4*ty;
    const int n0 = blockIdx.x * 64;

    for (int i = t; i < 64*256; i += 256) {
        int e = i >> 8, k = i & 255;
        int node = n0 + e;
        float v = 0.f;
        if (node < NN)
            v = (k < HID) ? g_mi[node*HID + k] : h[node*HID + (k-HID)];
        zs[k*LDA + e] = v;
    }

    float acc[4][8];
    zero_acc(acc);
    gemm4<256,64,false>(zs, Wn1, ws, t, ty, c0, acc);
    #pragma unroll
    for (int r=0;r<4;r++)
        #pragma unroll
        for (int j=0;j<8;j++)
            acc[r][j] = siluf_(acc[r][j] + bn1[c0+j]);

    __syncthreads();   // all done reading zs
    #pragma unroll
    for (int j=0;j<8;j++)
        st_col4(zs, c0+j, ty, make_float4(acc[0][j],acc[1][j],acc[2][j],acc[3][j]));

    zero_acc(acc);
    gemm4<128,64,true>(zs, Wn2, ws, t, ty, c0, acc);

    #pragma unroll
    for (int r=0;r<4;r++) {
        int node = n0 + r0 + r;
        if (node < NN) {
            float4 h0 = ld4(h + node*HID + c0), h1 = ld4(h + node*HID + c0 + 4);
            *(float4*)(out + node*HID + c0) = make_float4(
                h0.x + acc[r][0] + bn2[c0+0], h0.y + acc[r][1] + bn2[c0+1],
                h0.z + acc[r][2] + bn2[c0+2], h0.w + acc[r][3] + bn2[c0+3]);
            *(float4*)(out + node*HID + c0 + 4) = make_float4(
                h1.x + acc[r][4] + bn2[c0+4], h1.y + acc[r][5] + bn2[c0+5],
                h1.z + acc[r][6] + bn2[c0+6], h1.w + acc[r][7] + bn2[c0+7]);
        }
    }
    if (t < 64*3) {
        int e = t/3, a = t - 3*e;
        int node = n0 + e;
        if (node < NN)
            out[XOUT_OFF + node*3 + a] = x[node*3 + a] + g_dx[node*3 + a]*mask[node];
    }
}

extern "C" void kernel_launch(void* const* d_in, const int* in_sizes, int n_in,
                              void* d_out, int out_size)
{
    const float* h         = (const float*)d_in[0];
    const float* x         = (const float*)d_in[1];
    const int*   eidx      = (const int*)d_in[2];   // int32 (jax x64 disabled)
    const float* mask      = (const float*)d_in[3];
    const float* edge_attr = (const float*)d_in[4];
    const float* We1  = (const float*)d_in[5];
    const float* be1  = (const float*)d_in[6];
    const float* We2  = (const float*)d_in[7];
    const float* be2  = (const float*)d_in[8];
    const float* Winf = (const float*)d_in[9];
    const float* binf = (const float*)d_in[10];
    const float* Wx1  = (const float*)d_in[11];
    const float* bx1  = (const float*)d_in[12];
    const float* Wx2  = (const float*)d_in[13];
    const float* Wn1  = (const float*)d_in[14];
    const float* bn1  = (const float*)d_in[15];
    const float* Wn2  = (const float*)d_in[16];
    const float* bn2  = (const float*)d_in[17];
    float* out = (float*)d_out;

    cudaFuncSetAttribute(pre_kernel,  cudaFuncAttributeMaxDynamicSharedMemorySize, PRE_SMEM);
    cudaFuncSetAttribute(edge_kernel, cudaFuncAttributeMaxDynamicSharedMemorySize, EDGE_SMEM);
    cudaFuncSetAttribute(node_kernel, cudaFuncAttributeMaxDynamicSharedMemorySize, NODE_SMEM);

    zero_kernel<<<(NN*HID/4 + 255)/256, 256>>>();
    pre_kernel <<<(NN + 63)/64, 256, PRE_SMEM>>>(h, We1);
    edge_kernel<<<NE/64, 256, EDGE_SMEM>>>(x, eidx, edge_attr,
                                           We1, be1, We2, be2, Winf, binf,
                                           Wx1, bx1, Wx2);
    node_kernel<<<(NN + 63)/64, 256, NODE_SMEM>>>(h, x, mask,
                                                  Wn1, bn1, Wn2, bn2, out);
}

// round 6
// speedup vs baseline: 4.2020x; 1.2530x over previous
#include <cuda_runtime.h>

#define NN   50000
#define NE   640000
#define HID  128
#define NG   20
#define EF   4
#define XOUT_OFF (NN*HID)
#define LDA  68
#define LDA4 17

typedef unsigned long long u64;

// scratch
__device__ __align__(16) float g_mi[NN*HID];
__device__ __align__(16) float g_p [NN*HID];
__device__ __align__(16) float g_q [NN*HID];
__device__ __align__(16) float g_dx[NN*3];

__device__ __forceinline__ float sigmoidf_(float v){ return 1.f/(1.f+__expf(-v)); }
__device__ __forceinline__ float siluf_(float v){ return v/(1.f+__expf(-v)); }
__device__ __forceinline__ int clampi(int v){ return v < 0 ? 0 : (v >= NN ? NN-1 : v); }
__device__ __forceinline__ float4 ld4(const float* p){ return *(const float4*)p; }

__device__ __forceinline__ void red_add_v4(float* a, float x, float y, float z, float w){
    asm volatile("red.global.add.v4.f32 [%0], {%1,%2,%3,%4};"
                 :: "l"(a), "f"(x), "f"(y), "f"(z), "f"(w) : "memory");
}

#define PK2(d,lo,hi)  asm("mov.b64 %0, {%1,%2};" : "=l"(d) : "f"(lo), "f"(hi))
#define UPK2(lo,hi,s) asm("mov.b64 {%0,%1}, %2;" : "=f"(lo), "=f"(hi) : "l"(s))
#define FMA2(d,a,b)   asm("fma.rn.f32x2 %0, %1, %2, %0;" : "+l"(d) : "l"(a), "l"(b))

__global__ void zero_kernel() {
    int i = blockIdx.x*256 + threadIdx.x;
    if (i < NN*HID/4) ((float4*)g_mi)[i] = make_float4(0.f,0.f,0.f,0.f);
    if (i < NN*3/4)   ((float4*)g_dx)[i] = make_float4(0.f,0.f,0.f,0.f);
}

// ---------------- SIMT gemm helper for pre/node (unchanged R4) ----------
__device__ __forceinline__ void zero_acc(float acc[4][8]){
    #pragma unroll
    for (int r=0;r<4;r++)
        #pragma unroll
        for (int j=0;j<8;j++) acc[r][j]=0.f;
}
__device__ __forceinline__ void st_col4(float* buf, int c, int ty, float4 v){
    ((float4*)buf)[c*LDA4 + (ty ^ ((c>>3)&15))] = v;
}
template<int K, int KC, bool SWZ>
__device__ __forceinline__ void gemm4(const float* __restrict__ src,
                                      const float* __restrict__ Wg,
                                      float* ws, int t, int ty, int c0,
                                      float acc[4][8])
{
    const float4* s4 = (const float4*)src;
    for (int kb = 0; kb < K; kb += KC) {
        __syncthreads();
        {
            const float4* Wg4 = (const float4*)(Wg + kb*128);
            float4* ws4 = (float4*)ws;
            for (int i = t; i < KC*32; i += 256) ws4[i] = Wg4[i];
        }
        __syncthreads();
        #pragma unroll 8
        for (int kk = 0; kk < KC; ++kk) {
            int k = kb + kk;
            float4 a = SWZ ? s4[k*LDA4 + (ty ^ ((k>>3)&15))]
                           : s4[k*LDA4 + ty];
            const float4* wr = (const float4*)(ws + kk*128 + c0);
            float4 w0 = wr[0], w1 = wr[1];
            float av[4] = {a.x,a.y,a.z,a.w};
            float wv[8] = {w0.x,w0.y,w0.z,w0.w,w1.x,w1.y,w1.z,w1.w};
            #pragma unroll
            for (int r=0;r<4;r++)
                #pragma unroll
                for (int j=0;j<8;j++) acc[r][j] += av[r]*wv[j];
        }
    }
}

// ---------------- node precompute: P = h@We1[0:128], Q = h@We1[128:256] ----
#define PRE_SMEM ((128*LDA + 64*128)*4)
__global__ __launch_bounds__(256,2) void pre_kernel(
    const float* __restrict__ h, const float* __restrict__ We1)
{
    extern __shared__ float sm[];
    float* hs = sm;
    float* ws = sm + 128*LDA;
    const int t = threadIdx.x;
    const int tx = t & 15, ty = t >> 4;
    const int c0 = 8*tx, r0 = 4*ty;
    const int n0 = blockIdx.x * 64;

    for (int i = t; i < 64*128; i += 256) {
        int e = i >> 7, k = i & 127;
        int node = n0 + e;
        hs[k*LDA + e] = (node < NN) ? h[node*HID + k] : 0.f;
    }

    float acc[4][8];
    zero_acc(acc);
    gemm4<128,64,false>(hs, We1, ws, t, ty, c0, acc);
    #pragma unroll
    for (int r=0;r<4;r++) {
        int node = n0 + r0 + r;
        if (node < NN) {
            *(float4*)(g_p + node*HID + c0)     = make_float4(acc[r][0],acc[r][1],acc[r][2],acc[r][3]);
            *(float4*)(g_p + node*HID + c0 + 4) = make_float4(acc[r][4],acc[r][5],acc[r][6],acc[r][7]);
        }
    }
    zero_acc(acc);
    gemm4<128,64,false>(hs, We1 + 128*128, ws, t, ty, c0, acc);
    #pragma unroll
    for (int r=0;r<4;r++) {
        int node = n0 + r0 + r;
        if (node < NN) {
            *(float4*)(g_q + node*HID + c0)     = make_float4(acc[r][0],acc[r][1],acc[r][2],acc[r][3]);
            *(float4*)(g_q + node*HID + c0 + 4) = make_float4(acc[r][4],acc[r][5],acc[r][6],acc[r][7]);
        }
    }
}

// ---------------- edge kernel: 128 edges/CTA, 8x8 tiles, f32x2 FMA --------
// dyn smem: t1s [128][132] floats (k-major, swizzled f4 rows) @ 0 (16896 floats)
//           ws  [32][128]  floats                             @ 16896 (4096)
// fe [24][132] aliases t1s rows 0..23 (dead before t1s writes).
#define EDGE_SMEM ((16896 + 4096)*4)

// f32x2 mainloop: acc[8][4] pairs; cols c0..c0+7, rows 8*ty..+7
template<int KTOT, int KC>
__device__ __forceinline__ void gemm_x2(const float4* __restrict__ t1s4,
                                        float4* __restrict__ ws4,
                                        const float* __restrict__ Wg,
                                        int t, int tx, int ty, u64 acc[8][4])
{
    for (int kb = 0; kb < KTOT; kb += KC) {
        __syncthreads();
        {
            const float4* Wg4 = (const float4*)(Wg + kb*128);
            for (int i = t; i < KC*32; i += 256) ws4[i] = Wg4[i];
        }
        __syncthreads();
        #pragma unroll 8
        for (int kk = 0; kk < KC; ++kk) {
            int k = kb + kk;
            int swz = (k>>3)&7;
            float4 a0 = t1s4[k*33 + ((2*ty)   ^ swz)];
            float4 a1 = t1s4[k*33 + ((2*ty+1) ^ swz)];
            float4 w0 = ws4[kk*32 + 2*tx];
            float4 w1 = ws4[kk*32 + 2*tx + 1];
            u64 wp[4];
            PK2(wp[0], w0.x, w0.y); PK2(wp[1], w0.z, w0.w);
            PK2(wp[2], w1.x, w1.y); PK2(wp[3], w1.z, w1.w);
            float av[8] = {a0.x,a0.y,a0.z,a0.w,a1.x,a1.y,a1.z,a1.w};
            #pragma unroll
            for (int r=0;r<8;r++) {
                u64 ap; PK2(ap, av[r], av[r]);
                #pragma unroll
                for (int j=0;j<4;j++) FMA2(acc[r][j], ap, wp[j]);
            }
        }
    }
}

__device__ __forceinline__ void zero_acc2(u64 acc[8][4]){
    #pragma unroll
    for (int r=0;r<8;r++)
        #pragma unroll
        for (int j=0;j<4;j++) acc[r][j]=0ull;
}
__device__ __forceinline__ void unpack_acc(const u64 acc[8][4], float m[8][8]){
    #pragma unroll
    for (int r=0;r<8;r++)
        #pragma unroll
        for (int j=0;j<4;j++) UPK2(m[r][2*j], m[r][2*j+1], acc[r][j]);
}
// store col k of next-gemm A: rows 8ty..+7 (two f4), swizzle on (k>>3)&7
__device__ __forceinline__ void st_colk(float4* t1s4, int k, int ty, float4 v0, float4 v1){
    int swz = (k>>3)&7;
    t1s4[k*33 + ((2*ty)   ^ swz)] = v0;
    t1s4[k*33 + ((2*ty+1) ^ swz)] = v1;
}

__global__ __launch_bounds__(256,2) void edge_kernel(
    const float* __restrict__ x,
    const int* __restrict__ eidx, const float* __restrict__ edge_attr,
    const float* __restrict__ We1, const float* __restrict__ be1,
    const float* __restrict__ We2, const float* __restrict__ be2,
    const float* __restrict__ Winf, const float* __restrict__ binf,
    const float* __restrict__ Wx1, const float* __restrict__ bx1,
    const float* __restrict__ Wx2)
{
    extern __shared__ float sm[];
    float*  fe   = sm;                       // [24][132], aliases t1s
    float4* t1s4 = (float4*)sm;              // [128][33] f4 rows
    float*  ws   = sm + 16896;               // [KC][128]
    float4* ws4  = (float4*)ws;
    __shared__ int   dstl[128], srcl[128];
    __shared__ float rels[3][128], dsv[128];
    __shared__ float be1s[128], be2s[128], bx1s[128], winfs[128], wx2s[128];

    const int t  = threadIdx.x;
    const int tx = t & 15, ty = t >> 4;
    const int c0 = 8*tx, r0 = 8*ty;
    const long e0 = (long)blockIdx.x * 128;

    if (t < 128) {
        int s = clampi(eidx[e0 + t]);
        int d = clampi(eidx[NE + e0 + t]);
        srcl[t] = s; dstl[t] = d;
        float d0 = x[d*3+0]-x[s*3+0];
        float d1 = x[d*3+1]-x[s*3+1];
        float d2 = x[d*3+2]-x[s*3+2];
        rels[0][t]=d0; rels[1][t]=d1; rels[2][t]=d2;
        dsv[t] = sqrtf(d0*d0 + d1*d1 + d2*d2 + 1e-8f);
        be1s[t]=be1[t]; be2s[t]=be2[t]; bx1s[t]=bx1[t];
        winfs[t]=Winf[t]; wx2s[t]=Wx2[t];
    }
    __syncthreads();

    // feature tile fe[24][132]: gauss(d)[20] | edge_attr[4]
    const float step  = 10.f/19.f;
    const float coeff = -0.5f/(step*step);
    for (int i = t; i < 24*128; i += 256) {
        int e = i & 127, k = i >> 7;
        float v;
        if (k < NG) { float dd = dsv[e] - step*(float)k; v = __expf(coeff*dd*dd); }
        else        { v = edge_attr[(e0+e)*EF + (k-NG)]; }
        fe[k*132 + e] = v;
    }

    u64 acc[8][4];
    float m[8][8];

    // ---- GEMM1 (K=24): t1 = silu(fe @ We1r + P[dst] + Q[src] + be1) ----
    zero_acc2(acc);
    {
        // stage We1 remainder rows (24x128)
        __syncthreads();
        {
            const float4* Wg4 = (const float4*)(We1 + 256*128);
            for (int i = t; i < 24*32; i += 256) ws4[i] = Wg4[i];
        }
        __syncthreads();
        #pragma unroll 8
        for (int kk = 0; kk < 24; ++kk) {
            float4 a0 = t1s4[kk*33 + 2*ty];      // fe, no swizzle
            float4 a1 = t1s4[kk*33 + 2*ty + 1];
            float4 w0 = ws4[kk*32 + 2*tx];
            float4 w1 = ws4[kk*32 + 2*tx + 1];
            u64 wp[4];
            PK2(wp[0], w0.x, w0.y); PK2(wp[1], w0.z, w0.w);
            PK2(wp[2], w1.x, w1.y); PK2(wp[3], w1.z, w1.w);
            float av[8] = {a0.x,a0.y,a0.z,a0.w,a1.x,a1.y,a1.z,a1.w};
            #pragma unroll
            for (int r=0;r<8;r++) {
                u64 ap; PK2(ap, av[r], av[r]);
                #pragma unroll
                for (int j=0;j<4;j++) FMA2(acc[r][j], ap, wp[j]);
            }
        }
    }
    unpack_acc(acc, m);
    __syncthreads();     // fe (aliasing t1s) dead from here
    {
        #pragma unroll
        for (int r=0;r<8;r++) {
            int mm = r0 + r;
            int dn = dstl[mm], sn = srcl[mm];
            float4 p0 = ld4(g_p + dn*HID + c0), p1 = ld4(g_p + dn*HID + c0 + 4);
            float4 q0 = ld4(g_q + sn*HID + c0), q1 = ld4(g_q + sn*HID + c0 + 4);
            m[r][0]=siluf_(m[r][0]+p0.x+q0.x+be1s[c0+0]);
            m[r][1]=siluf_(m[r][1]+p0.y+q0.y+be1s[c0+1]);
            m[r][2]=siluf_(m[r][2]+p0.z+q0.z+be1s[c0+2]);
            m[r][3]=siluf_(m[r][3]+p0.w+q0.w+be1s[c0+3]);
            m[r][4]=siluf_(m[r][4]+p1.x+q1.x+be1s[c0+4]);
            m[r][5]=siluf_(m[r][5]+p1.y+q1.y+be1s[c0+5]);
            m[r][6]=siluf_(m[r][6]+p1.z+q1.z+be1s[c0+6]);
            m[r][7]=siluf_(m[r][7]+p1.w+q1.w+be1s[c0+7]);
        }
        // transpose-store t1 into t1s: col k = c0+j, rows r0..r0+7
        #pragma unroll
        for (int j=0;j<8;j++)
            st_colk(t1s4, c0+j, ty,
                    make_float4(m[0][j],m[1][j],m[2][j],m[3][j]),
                    make_float4(m[4][j],m[5][j],m[6][j],m[7][j]));
    }

    // ---- GEMM2: mij = silu(t1 @ We2 + be2) ----
    zero_acc2(acc);
    gemm_x2<128,32>(t1s4, ws4, We2, t, tx, ty, acc);
    unpack_acc(acc, m);
    {
        #pragma unroll
        for (int r=0;r<8;r++)
            #pragma unroll
            for (int j=0;j<8;j++)
                m[r][j] = siluf_(m[r][j] + be2s[c0+j]);
        // eij = sigmoid(<mij, Winf> + binf): reduce over 16 tx lanes
        float p[8];
        #pragma unroll
        for (int r=0;r<8;r++) {
            float s = 0.f;
            #pragma unroll
            for (int j=0;j<8;j++) s += m[r][j]*winfs[c0+j];
            p[r] = s;
        }
        #pragma unroll
        for (int off=8; off; off >>= 1)
            #pragma unroll
            for (int r=0;r<8;r++) p[r] += __shfl_xor_sync(0xffffffffu, p[r], off);
        float bi = binf[0];
        #pragma unroll
        for (int r=0;r<8;r++) {
            float eg = sigmoidf_(p[r] + bi);
            int dn = dstl[r0+r];
            red_add_v4(&g_mi[dn*HID + c0],     m[r][0]*eg, m[r][1]*eg, m[r][2]*eg, m[r][3]*eg);
            red_add_v4(&g_mi[dn*HID + c0 + 4], m[r][4]*eg, m[r][5]*eg, m[r][6]*eg, m[r][7]*eg);
        }
    }
    __syncthreads();     // everyone done reading t1s (GEMM2 mainloop)
    #pragma unroll
    for (int j=0;j<8;j++)
        st_colk(t1s4, c0+j, ty,
                make_float4(m[0][j],m[1][j],m[2][j],m[3][j]),
                make_float4(m[4][j],m[5][j],m[6][j],m[7][j]));

    // ---- GEMM3: xg = tanh(silu(mij @ Wx1 + bx1) . Wx2) ----
    zero_acc2(acc);
    gemm_x2<128,32>(t1s4, ws4, Wx1, t, tx, ty, acc);
    unpack_acc(acc, m);
    {
        float q[8];
        #pragma unroll
        for (int r=0;r<8;r++) {
            float s = 0.f;
            #pragma unroll
            for (int j=0;j<8;j++) s += siluf_(m[r][j] + bx1s[c0+j]) * wx2s[c0+j];
            q[r] = s;
        }
        #pragma unroll
        for (int off=8; off; off >>= 1)
            #pragma unroll
            for (int r=0;r<8;r++) q[r] += __shfl_xor_sync(0xffffffffu, q[r], off);
        if (tx < 3) {
            #pragma unroll
            for (int r=0;r<8;r++) {
                int mm = r0 + r;
                float s = tanhf(q[r]) / (dsv[mm] + 1.f);
                atomicAdd(&g_dx[dstl[mm]*3 + tx], rels[tx][mm]*s);
            }
        }
    }
}

// ---------------- node kernel (unchanged R4) ----------------
#define NODE_SMEM ((256*LDA + 64*128)*4)
__global__ __launch_bounds__(256,2) void node_kernel(
    const float* __restrict__ h, const float* __restrict__ x,
    const float* __restrict__ mask,
    const float* __restrict__ Wn1, const float* __restrict__ bn1,
    const float* __restrict__ Wn2, const float* __restrict__ bn2,
    float* __restrict__ out)
{
    extern __shared__ float sm[];
    float* zs = sm;
    float* ws = sm + 256*LDA;

    const int t  = threadIdx.x;
    const int tx = t & 15, ty = t >> 4;
    const int c0 = 8*tx, r0 = 4*ty;
    const int n0 = blockIdx.x * 64;

    for (int i = t; i < 64*256; i += 256) {
        int e = i >> 8, k = i & 255;
        int node = n0 + e;
        float v = 0.f;
        if (node < NN)
            v = (k < HID) ? g_mi[node*HID + k] : h[node*HID + (k-HID)];
        zs[k*LDA + e] = v;
    }

    float acc[4][8];
    zero_acc(acc);
    gemm4<256,64,false>(zs, Wn1, ws, t, ty, c0, acc);
    #pragma unroll
    for (int r=0;r<4;r++)
        #pragma unroll
        for (int j=0;j<8;j++)
            acc[r][j] = siluf_(acc[r][j] + bn1[c0+j]);

    __syncthreads();
    #pragma unroll
    for (int j=0;j<8;j++)
        st_col4(zs, c0+j, ty, make_float4(acc[0][j],acc[1][j],acc[2][j],acc[3][j]));

    zero_acc(acc);
    gemm4<128,64,true>(zs, Wn2, ws, t, ty, c0, acc);

    #pragma unroll
    for (int r=0;r<4;r++) {
        int node = n0 + r0 + r;
        if (node < NN) {
            float4 h0 = ld4(h + node*HID + c0), h1 = ld4(h + node*HID + c0 + 4);
            *(float4*)(out + node*HID + c0) = make_float4(
                h0.x + acc[r][0] + bn2[c0+0], h0.y + acc[r][1] + bn2[c0+1],
                h0.z + acc[r][2] + bn2[c0+2], h0.w + acc[r][3] + bn2[c0+3]);
            *(float4*)(out + node*HID + c0 + 4) = make_float4(
                h1.x + acc[r][4] + bn2[c0+4], h1.y + acc[r][5] + bn2[c0+5],
                h1.z + acc[r][6] + bn2[c0+6], h1.w + acc[r][7] + bn2[c0+7]);
        }
    }
    if (t < 64*3) {
        int e = t/3, a = t - 3*e;
        int node = n0 + e;
        if (node < NN)
            out[XOUT_OFF + node*3 + a] = x[node*3 + a] + g_dx[node*3 + a]*mask[node];
    }
}

extern "C" void kernel_launch(void* const* d_in, const int* in_sizes, int n_in,
                              void* d_out, int out_size)
{
    const float* h         = (const float*)d_in[0];
    const float* x         = (const float*)d_in[1];
    const int*   eidx      = (const int*)d_in[2];   // int32 (jax x64 disabled)
    const float* mask      = (const float*)d_in[3];
    const float* edge_attr = (const float*)d_in[4];
    const float* We1  = (const float*)d_in[5];
    const float* be1  = (const float*)d_in[6];
    const float* We2  = (const float*)d_in[7];
    const float* be2  = (const float*)d_in[8];
    const float* Winf = (const float*)d_in[9];
    const float* binf = (const float*)d_in[10];
    const float* Wx1  = (const float*)d_in[11];
    const float* bx1  = (const float*)d_in[12];
    const float* Wx2  = (const float*)d_in[13];
    const float* Wn1  = (const float*)d_in[14];
    const float* bn1  = (const float*)d_in[15];
    const float* Wn2  = (const float*)d_in[16];
    const float* bn2  = (const float*)d_in[17];
    float* out = (float*)d_out;

    cudaFuncSetAttribute(pre_kernel,  cudaFuncAttributeMaxDynamicSharedMemorySize, PRE_SMEM);
    cudaFuncSetAttribute(edge_kernel, cudaFuncAttributeMaxDynamicSharedMemorySize, EDGE_SMEM);
    cudaFuncSetAttribute(node_kernel, cudaFuncAttributeMaxDynamicSharedMemorySize, NODE_SMEM);

    zero_kernel<<<(NN*HID/4 + 255)/256, 256>>>();
    pre_kernel <<<(NN + 63)/64, 256, PRE_SMEM>>>(h, We1);
    edge_kernel<<<NE/128, 256, EDGE_SMEM>>>(x, eidx, edge_attr,
                                            We1, be1, We2, be2, Winf, binf,
                                            Wx1, bx1, Wx2);
    node_kernel<<<(NN + 63)/64, 256, NODE_SMEM>>>(h, x, mask,
                                                  Wn1, bn1, Wn2, bn2, out);
}

// round 7
// speedup vs baseline: 4.6372x; 1.1036x over previous
#include <cuda_runtime.h>

#define NN   50000
#define NE   640000
#define HID  128
#define NG   20
#define EF   4
#define XOUT_OFF (NN*HID)
#define LDA  68
#define LDA4 17

typedef unsigned long long u64;

// scratch
__device__ __align__(16) float g_mi[NN*HID];
__device__ __align__(16) float g_p [NN*HID];
__device__ __align__(16) float g_q [NN*HID];
__device__ __align__(16) float g_dx[NN*3];

__device__ __forceinline__ float sigmoidf_(float v){ return 1.f/(1.f+__expf(-v)); }
__device__ __forceinline__ float siluf_(float v){ return v/(1.f+__expf(-v)); }
__device__ __forceinline__ int clampi(int v){ return v < 0 ? 0 : (v >= NN ? NN-1 : v); }
__device__ __forceinline__ float4 ld4(const float* p){ return *(const float4*)p; }

__device__ __forceinline__ void red_add_v4(float* a, float x, float y, float z, float w){
    asm volatile("red.global.add.v4.f32 [%0], {%1,%2,%3,%4};"
                 :: "l"(a), "f"(x), "f"(y), "f"(z), "f"(w) : "memory");
}

#define PK2(d,lo,hi)  asm("mov.b64 %0, {%1,%2};" : "=l"(d) : "f"(lo), "f"(hi))
#define UPK2(lo,hi,s) asm("mov.b64 {%0,%1}, %2;" : "=f"(lo), "=f"(hi) : "l"(s))
#define FMA2(d,a,b)   asm("fma.rn.f32x2 %0, %1, %2, %0;" : "+l"(d) : "l"(a), "l"(b))

__device__ __forceinline__ unsigned smem_u32(const void* p){
    unsigned a;
    asm("{ .reg .u64 t; cvta.to.shared.u64 t, %1; cvt.u32.u64 %0, t; }" : "=r"(a) : "l"(p));
    return a;
}
__device__ __forceinline__ void lds2u64(u64& a, u64& b, unsigned addr){
    asm volatile("ld.shared.v2.u64 {%0,%1}, [%2];" : "=l"(a), "=l"(b) : "r"(addr));
}
__device__ __forceinline__ void sts_u64(unsigned addr, u64 v){
    asm volatile("st.shared.u64 [%0], %1;" :: "r"(addr), "l"(v));
}
__device__ __forceinline__ void sts2u64(unsigned addr, u64 a, u64 b){
    asm volatile("st.shared.v2.u64 [%0], {%1,%2};" :: "r"(addr), "l"(a), "l"(b));
}

__global__ void zero_kernel() {
    int i = blockIdx.x*256 + threadIdx.x;
    if (i < NN*HID/4) ((float4*)g_mi)[i] = make_float4(0.f,0.f,0.f,0.f);
    if (i < NN*3/4)   ((float4*)g_dx)[i] = make_float4(0.f,0.f,0.f,0.f);
}

// ---------------- row-pair FFMA2 gemm for pre/node: rows 4*ty..+3 ----------
template<int K, int KC, bool SWZ>
__device__ __forceinline__ void gemm4b(unsigned src_su, float4* __restrict__ ws4,
                                       const float* __restrict__ Wg,
                                       int t, int tx, int ty, u64 acc[2][8])
{
    for (int kb = 0; kb < K; kb += KC) {
        __syncthreads();
        {
            const float4* Wg4 = (const float4*)(Wg + kb*128);
            for (int i = t; i < KC*32; i += 256) ws4[i] = Wg4[i];
        }
        __syncthreads();
        #pragma unroll 8
        for (int kk = 0; kk < KC; ++kk) {
            int k = kb + kk;
            int slot = SWZ ? (ty ^ ((k>>3)&15)) : ty;
            u64 a0, a1;
            lds2u64(a0, a1, src_su + (unsigned)(k*LDA4 + slot)*16u);
            float4 w0 = ws4[kk*32 + 2*tx], w1 = ws4[kk*32 + 2*tx + 1];
            float wv[8] = {w0.x,w0.y,w0.z,w0.w,w1.x,w1.y,w1.z,w1.w};
            u64 wp[8];
            #pragma unroll
            for (int j=0;j<8;j++) PK2(wp[j], wv[j], wv[j]);
            #pragma unroll
            for (int j=0;j<8;j++){ FMA2(acc[0][j], a0, wp[j]); FMA2(acc[1][j], a1, wp[j]); }
        }
    }
}
__device__ __forceinline__ void zacc2x8(u64 acc[2][8]){
    #pragma unroll
    for (int p=0;p<2;p++)
        #pragma unroll
        for (int j=0;j<8;j++) acc[p][j]=0ull;
}

// ---------------- node precompute: P = h@We1[0:128], Q = h@We1[128:256] ----
#define PRE_SMEM ((128*LDA + 64*128)*4)
__global__ __launch_bounds__(256,2) void pre_kernel(
    const float* __restrict__ h, const float* __restrict__ We1)
{
    extern __shared__ float sm[];
    float*  hs  = sm;                  // [128][LDA]
    float4* ws4 = (float4*)(sm + 128*LDA);
    const int t = threadIdx.x;
    const int tx = t & 15, ty = t >> 4;
    const int c0 = 8*tx, r0 = 4*ty;
    const int n0 = blockIdx.x * 64;
    const unsigned su = smem_u32(sm);

    for (int i = t; i < 64*128; i += 256) {
        int e = i >> 7, k = i & 127;
        int node = n0 + e;
        hs[k*LDA + e] = (node < NN) ? h[node*HID + k] : 0.f;
    }

    u64 acc[2][8];
    float lo[8], hi[8];

    zacc2x8(acc);
    gemm4b<128,64,false>(su, ws4, We1, t, tx, ty, acc);
    #pragma unroll
    for (int p=0;p<2;p++) {
        #pragma unroll
        for (int j=0;j<8;j++) UPK2(lo[j], hi[j], acc[p][j]);
        int nA = n0 + r0 + 2*p, nB = nA + 1;
        if (nA < NN) {
            *(float4*)(g_p + nA*HID + c0)   = make_float4(lo[0],lo[1],lo[2],lo[3]);
            *(float4*)(g_p + nA*HID + c0+4) = make_float4(lo[4],lo[5],lo[6],lo[7]);
        }
        if (nB < NN) {
            *(float4*)(g_p + nB*HID + c0)   = make_float4(hi[0],hi[1],hi[2],hi[3]);
            *(float4*)(g_p + nB*HID + c0+4) = make_float4(hi[4],hi[5],hi[6],hi[7]);
        }
    }
    zacc2x8(acc);
    gemm4b<128,64,false>(su, ws4, We1 + 128*128, t, tx, ty, acc);
    #pragma unroll
    for (int p=0;p<2;p++) {
        #pragma unroll
        for (int j=0;j<8;j++) UPK2(lo[j], hi[j], acc[p][j]);
        int nA = n0 + r0 + 2*p, nB = nA + 1;
        if (nA < NN) {
            *(float4*)(g_q + nA*HID + c0)   = make_float4(lo[0],lo[1],lo[2],lo[3]);
            *(float4*)(g_q + nA*HID + c0+4) = make_float4(lo[4],lo[5],lo[6],lo[7]);
        }
        if (nB < NN) {
            *(float4*)(g_q + nB*HID + c0)   = make_float4(hi[0],hi[1],hi[2],hi[3]);
            *(float4*)(g_q + nB*HID + c0+4) = make_float4(hi[4],hi[5],hi[6],hi[7]);
        }
    }
}

// ---------------- edge kernel: 128 edges/CTA, row-pair FFMA2 --------------
// dyn smem: t1s [128 cols][33 f4 rows] @ 0 (16896 floats, swizzled)
//           ws  [64][128] floats       @ 16896 (8192 floats)
// fe [24][132] aliases t1s rows (dead before t1s writes).
#define EDGE_SMEM ((16896 + 8192)*4)

// rows pairs p=0..3 -> rows r0+2p, r0+2p+1 (r0=8*ty); cols c0..c0+7 (c0=8*tx)
template<int KTOT, int KC>
__device__ __forceinline__ void gemm_x2(unsigned t1su, float4* __restrict__ ws4,
                                        const float* __restrict__ Wg,
                                        int t, int tx, int ty, u64 acc[4][8])
{
    for (int kb = 0; kb < KTOT; kb += KC) {
        __syncthreads();
        {
            const float4* Wg4 = (const float4*)(Wg + kb*128);
            for (int i = t; i < KC*32; i += 256) ws4[i] = Wg4[i];
        }
        __syncthreads();
        #pragma unroll 8
        for (int kk = 0; kk < KC; ++kk) {
            int k = kb + kk;
            int swz = (k>>3)&7;
            u64 a01,a23,a45,a67;
            lds2u64(a01,a23, t1su + (unsigned)(k*33 + ((2*ty)  ^swz))*16u);
            lds2u64(a45,a67, t1su + (unsigned)(k*33 + ((2*ty+1)^swz))*16u);
            float4 w0 = ws4[kk*32 + 2*tx], w1 = ws4[kk*32 + 2*tx + 1];
            float wv[8] = {w0.x,w0.y,w0.z,w0.w,w1.x,w1.y,w1.z,w1.w};
            u64 wp[8];
            #pragma unroll
            for (int j=0;j<8;j++) PK2(wp[j], wv[j], wv[j]);
            #pragma unroll
            for (int j=0;j<8;j++){
                FMA2(acc[0][j], a01, wp[j]);
                FMA2(acc[1][j], a23, wp[j]);
                FMA2(acc[2][j], a45, wp[j]);
                FMA2(acc[3][j], a67, wp[j]);
            }
        }
    }
}
__device__ __forceinline__ void zacc4x8(u64 acc[4][8]){
    #pragma unroll
    for (int p=0;p<4;p++)
        #pragma unroll
        for (int j=0;j<8;j++) acc[p][j]=0ull;
}
// u64 store of (rowpair p) for column k: f4 group g=2*ty+(p>>1), half p&1
__device__ __forceinline__ unsigned colk_addr(unsigned t1su, int k, int ty, int p){
    int swz = (k>>3)&7;
    return t1su + (unsigned)(k*33 + ((2*ty + (p>>1)) ^ swz))*16u + (unsigned)(p&1)*8u;
}

__global__ __launch_bounds__(256,2) void edge_kernel(
    const float* __restrict__ x,
    const int* __restrict__ eidx, const float* __restrict__ edge_attr,
    const float* __restrict__ We1, const float* __restrict__ be1,
    const float* __restrict__ We2, const float* __restrict__ be2,
    const float* __restrict__ Winf, const float* __restrict__ binf,
    const float* __restrict__ Wx1, const float* __restrict__ bx1,
    const float* __restrict__ Wx2)
{
    extern __shared__ float sm[];
    float*  fe   = sm;                       // [24][132] aliases t1s
    float4* ws4  = (float4*)(sm + 16896);
    __shared__ int   dstl[128], srcl[128];
    __shared__ float rels[3][128], dsv[128];
    __shared__ float be1s[128], be2s[128], bx1s[128], winfs[128], wx2s[128];

    const int t  = threadIdx.x;
    const int tx = t & 15, ty = t >> 4;
    const int c0 = 8*tx, r0 = 8*ty;
    const long e0 = (long)blockIdx.x * 128;
    const unsigned t1su = smem_u32(sm);

    if (t < 128) {
        int s = clampi(eidx[e0 + t]);
        int d = clampi(eidx[NE + e0 + t]);
        srcl[t] = s; dstl[t] = d;
        float d0 = x[d*3+0]-x[s*3+0];
        float d1 = x[d*3+1]-x[s*3+1];
        float d2 = x[d*3+2]-x[s*3+2];
        rels[0][t]=d0; rels[1][t]=d1; rels[2][t]=d2;
        dsv[t] = sqrtf(d0*d0 + d1*d1 + d2*d2 + 1e-8f);
        be1s[t]=be1[t]; be2s[t]=be2[t]; bx1s[t]=bx1[t];
        winfs[t]=Winf[t]; wx2s[t]=Wx2[t];
    }
    __syncthreads();

    // feature tile fe[24][132]: gauss(d)[20] | edge_attr[4]
    const float step  = 10.f/19.f;
    const float coeff = -0.5f/(step*step);
    for (int i = t; i < 24*128; i += 256) {
        int e = i & 127, k = i >> 7;
        float v;
        if (k < NG) { float dd = dsv[e] - step*(float)k; v = __expf(coeff*dd*dd); }
        else        { v = edge_attr[(e0+e)*EF + (k-NG)]; }
        fe[k*132 + e] = v;
    }

    u64 acc[4][8];
    float lo[8], hi[8];

    // ---- GEMM1 (K=24): t1 = silu(fe @ We1r + P[dst] + Q[src] + be1) ----
    zacc4x8(acc);
    {
        __syncthreads();
        {
            const float4* Wg4 = (const float4*)(We1 + 256*128);
            for (int i = t; i < 24*32; i += 256) ws4[i] = Wg4[i];
        }
        __syncthreads();
        #pragma unroll 8
        for (int kk = 0; kk < 24; ++kk) {
            u64 a01,a23,a45,a67;
            lds2u64(a01,a23, t1su + (unsigned)(kk*33 + 2*ty)*16u);
            lds2u64(a45,a67, t1su + (unsigned)(kk*33 + 2*ty+1)*16u);
            float4 w0 = ws4[kk*32 + 2*tx], w1 = ws4[kk*32 + 2*tx + 1];
            float wv[8] = {w0.x,w0.y,w0.z,w0.w,w1.x,w1.y,w1.z,w1.w};
            u64 wp[8];
            #pragma unroll
            for (int j=0;j<8;j++) PK2(wp[j], wv[j], wv[j]);
            #pragma unroll
            for (int j=0;j<8;j++){
                FMA2(acc[0][j], a01, wp[j]);
                FMA2(acc[1][j], a23, wp[j]);
                FMA2(acc[2][j], a45, wp[j]);
                FMA2(acc[3][j], a67, wp[j]);
            }
        }
    }
    __syncthreads();     // fe (aliasing t1s) dead from here
    #pragma unroll
    for (int p=0;p<4;p++) {
        #pragma unroll
        for (int j=0;j<8;j++) UPK2(lo[j], hi[j], acc[p][j]);
        int mA = r0 + 2*p, mB = mA + 1;
        {
            int dn = dstl[mA], sn = srcl[mA];
            float4 p0 = ld4(g_p + dn*HID + c0), p1 = ld4(g_p + dn*HID + c0 + 4);
            float4 q0 = ld4(g_q + sn*HID + c0), q1 = ld4(g_q + sn*HID + c0 + 4);
            lo[0]=siluf_(lo[0]+p0.x+q0.x+be1s[c0+0]); lo[1]=siluf_(lo[1]+p0.y+q0.y+be1s[c0+1]);
            lo[2]=siluf_(lo[2]+p0.z+q0.z+be1s[c0+2]); lo[3]=siluf_(lo[3]+p0.w+q0.w+be1s[c0+3]);
            lo[4]=siluf_(lo[4]+p1.x+q1.x+be1s[c0+4]); lo[5]=siluf_(lo[5]+p1.y+q1.y+be1s[c0+5]);
            lo[6]=siluf_(lo[6]+p1.z+q1.z+be1s[c0+6]); lo[7]=siluf_(lo[7]+p1.w+q1.w+be1s[c0+7]);
        }
        {
            int dn = dstl[mB], sn = srcl[mB];
            float4 p0 = ld4(g_p + dn*HID + c0), p1 = ld4(g_p + dn*HID + c0 + 4);
            float4 q0 = ld4(g_q + sn*HID + c0), q1 = ld4(g_q + sn*HID + c0 + 4);
            hi[0]=siluf_(hi[0]+p0.x+q0.x+be1s[c0+0]); hi[1]=siluf_(hi[1]+p0.y+q0.y+be1s[c0+1]);
            hi[2]=siluf_(hi[2]+p0.z+q0.z+be1s[c0+2]); hi[3]=siluf_(hi[3]+p0.w+q0.w+be1s[c0+3]);
            hi[4]=siluf_(hi[4]+p1.x+q1.x+be1s[c0+4]); hi[5]=siluf_(hi[5]+p1.y+q1.y+be1s[c0+5]);
            hi[6]=siluf_(hi[6]+p1.z+q1.z+be1s[c0+6]); hi[7]=siluf_(hi[7]+p1.w+q1.w+be1s[c0+7]);
        }
        #pragma unroll
        for (int j=0;j<8;j++) {
            u64 v; PK2(v, lo[j], hi[j]);
            sts_u64(colk_addr(t1su, c0+j, ty, p), v);
        }
    }

    // ---- GEMM2: mij = silu(t1 @ We2 + be2); eij; scatter; rewrite t1s ----
    zacc4x8(acc);
    gemm_x2<128,64>(t1su, ws4, We2, t, tx, ty, acc);
    __syncthreads();     // all mainloop reads of t1s done
    {
        float bi = binf[0];
        #pragma unroll
        for (int p=0;p<4;p++) {
            #pragma unroll
            for (int j=0;j<8;j++) UPK2(lo[j], hi[j], acc[p][j]);
            #pragma unroll
            for (int j=0;j<8;j++) {
                lo[j] = siluf_(lo[j] + be2s[c0+j]);
                hi[j] = siluf_(hi[j] + be2s[c0+j]);
            }
            float sA = 0.f, sB = 0.f;
            #pragma unroll
            for (int j=0;j<8;j++) { sA += lo[j]*winfs[c0+j]; sB += hi[j]*winfs[c0+j]; }
            #pragma unroll
            for (int off=8; off; off >>= 1) {
                sA += __shfl_xor_sync(0xffffffffu, sA, off);
                sB += __shfl_xor_sync(0xffffffffu, sB, off);
            }
            int mA = r0 + 2*p, mB = mA + 1;
            float egA = sigmoidf_(sA + bi), egB = sigmoidf_(sB + bi);
            int dnA = dstl[mA], dnB = dstl[mB];
            red_add_v4(&g_mi[dnA*HID + c0],     lo[0]*egA, lo[1]*egA, lo[2]*egA, lo[3]*egA);
            red_add_v4(&g_mi[dnA*HID + c0 + 4], lo[4]*egA, lo[5]*egA, lo[6]*egA, lo[7]*egA);
            red_add_v4(&g_mi[dnB*HID + c0],     hi[0]*egB, hi[1]*egB, hi[2]*egB, hi[3]*egB);
            red_add_v4(&g_mi[dnB*HID + c0 + 4], hi[4]*egB, hi[5]*egB, hi[6]*egB, hi[7]*egB);
            #pragma unroll
            for (int j=0;j<8;j++) {
                u64 v; PK2(v, lo[j], hi[j]);
                sts_u64(colk_addr(t1su, c0+j, ty, p), v);
            }
        }
    }

    // ---- GEMM3: xg = tanh(silu(mij @ Wx1 + bx1) . Wx2); coord scatter ----
    zacc4x8(acc);
    gemm_x2<128,64>(t1su, ws4, Wx1, t, tx, ty, acc);
    {
        #pragma unroll
        for (int p=0;p<4;p++) {
            #pragma unroll
            for (int j=0;j<8;j++) UPK2(lo[j], hi[j], acc[p][j]);
            float qA = 0.f, qB = 0.f;
            #pragma unroll
            for (int j=0;j<8;j++) {
                float b = bx1s[c0+j], w = wx2s[c0+j];
                qA += siluf_(lo[j] + b)*w;
                qB += siluf_(hi[j] + b)*w;
            }
            #pragma unroll
            for (int off=8; off; off >>= 1) {
                qA += __shfl_xor_sync(0xffffffffu, qA, off);
                qB += __shfl_xor_sync(0xffffffffu, qB, off);
            }
            if (tx < 3) {
                int mA = r0 + 2*p, mB = mA + 1;
                float sA = tanhf(qA) / (dsv[mA] + 1.f);
                float sB = tanhf(qB) / (dsv[mB] + 1.f);
                atomicAdd(&g_dx[dstl[mA]*3 + tx], rels[tx][mA]*sA);
                atomicAdd(&g_dx[dstl[mB]*3 + tx], rels[tx][mB]*sB);
            }
        }
    }
}

// ---------------- node kernel (row-pair FFMA2) ----------------
#define NODE_SMEM ((256*LDA + 64*128)*4)
__global__ __launch_bounds__(256,2) void node_kernel(
    const float* __restrict__ h, const float* __restrict__ x,
    const float* __restrict__ mask,
    const float* __restrict__ Wn1, const float* __restrict__ bn1,
    const float* __restrict__ Wn2, const float* __restrict__ bn2,
    float* __restrict__ out)
{
    extern __shared__ float sm[];
    float*  zs  = sm;                        // [256][LDA]
    float4* ws4 = (float4*)(sm + 256*LDA);
    const unsigned su = smem_u32(sm);

    const int t  = threadIdx.x;
    const int tx = t & 15, ty = t >> 4;
    const int c0 = 8*tx, r0 = 4*ty;
    const int n0 = blockIdx.x * 64;

    for (int i = t; i < 64*256; i += 256) {
        int e = i >> 8, k = i & 255;
        int node = n0 + e;
        float v = 0.f;
        if (node < NN)
            v = (k < HID) ? g_mi[node*HID + k] : h[node*HID + (k-HID)];
        zs[k*LDA + e] = v;
    }

    u64 acc[2][8];
    float lo0[8], hi0[8], lo1[8], hi1[8];

    zacc2x8(acc);
    gemm4b<256,64,false>(su, ws4, Wn1, t, tx, ty, acc);
    #pragma unroll
    for (int j=0;j<8;j++) { UPK2(lo0[j], hi0[j], acc[0][j]); UPK2(lo1[j], hi1[j], acc[1][j]); }
    #pragma unroll
    for (int j=0;j<8;j++) {
        float b = bn1[c0+j];
        lo0[j]=siluf_(lo0[j]+b); hi0[j]=siluf_(hi0[j]+b);
        lo1[j]=siluf_(lo1[j]+b); hi1[j]=siluf_(hi1[j]+b);
    }
    __syncthreads();   // everyone done reading zs
    #pragma unroll
    for (int j=0;j<8;j++) {
        int c = c0 + j;
        u64 u0, u1;
        PK2(u0, lo0[j], hi0[j]);
        PK2(u1, lo1[j], hi1[j]);
        sts2u64(su + (unsigned)(c*LDA4 + (ty ^ ((c>>3)&15)))*16u, u0, u1);
    }

    zacc2x8(acc);
    gemm4b<128,64,true>(su, ws4, Wn2, t, tx, ty, acc);

    #pragma unroll
    for (int p=0;p<2;p++) {
        float lo[8], hi[8];
        #pragma unroll
        for (int j=0;j<8;j++) UPK2(lo[j], hi[j], acc[p][j]);
        int nA = n0 + r0 + 2*p, nB = nA + 1;
        if (nA < NN) {
            float4 h0 = ld4(h + nA*HID + c0), h1 = ld4(h + nA*HID + c0 + 4);
            *(float4*)(out + nA*HID + c0) = make_float4(
                h0.x+lo[0]+bn2[c0+0], h0.y+lo[1]+bn2[c0+1],
                h0.z+lo[2]+bn2[c0+2], h0.w+lo[3]+bn2[c0+3]);
            *(float4*)(out + nA*HID + c0 + 4) = make_float4(
                h1.x+lo[4]+bn2[c0+4], h1.y+lo[5]+bn2[c0+5],
                h1.z+lo[6]+bn2[c0+6], h1.w+lo[7]+bn2[c0+7]);
        }
        if (nB < NN) {
            float4 h0 = ld4(h + nB*HID + c0), h1 = ld4(h + nB*HID + c0 + 4);
            *(float4*)(out + nB*HID + c0) = make_float4(
                h0.x+hi[0]+bn2[c0+0], h0.y+hi[1]+bn2[c0+1],
                h0.z+hi[2]+bn2[c0+2], h0.w+hi[3]+bn2[c0+3]);
            *(float4*)(out + nB*HID + c0 + 4) = make_float4(
                h1.x+hi[4]+bn2[c0+4], h1.y+hi[5]+bn2[c0+5],
                h1.z+hi[6]+bn2[c0+6], h1.w+hi[7]+bn2[c0+7]);
        }
    }
    if (t < 64*3) {
        int e = t/3, a = t - 3*e;
        int node = n0 + e;
        if (node < NN)
            out[XOUT_OFF + node*3 + a] = x[node*3 + a] + g_dx[node*3 + a]*mask[node];
    }
}

extern "C" void kernel_launch(void* const* d_in, const int* in_sizes, int n_in,
                              void* d_out, int out_size)
{
    const float* h         = (const float*)d_in[0];
    const float* x         = (const float*)d_in[1];
    const int*   eidx      = (const int*)d_in[2];   // int32 (jax x64 disabled)
    const float* mask      = (const float*)d_in[3];
    const float* edge_attr = (const float*)d_in[4];
    const float* We1  = (const float*)d_in[5];
    const float* be1  = (const float*)d_in[6];
    const float* We2  = (const float*)d_in[7];
    const float* be2  = (const float*)d_in[8];
    const float* Winf = (const float*)d_in[9];
    const float* binf = (const float*)d_in[10];
    const float* Wx1  = (const float*)d_in[11];
    const float* bx1  = (const float*)d_in[12];
    const float* Wx2  = (const float*)d_in[13];
    const float* Wn1  = (const float*)d_in[14];
    const float* bn1  = (const float*)d_in[15];
    const float* Wn2  = (const float*)d_in[16];
    const float* bn2  = (const float*)d_in[17];
    float* out = (float*)d_out;

    cudaFuncSetAttribute(pre_kernel,  cudaFuncAttributeMaxDynamicSharedMemorySize, PRE_SMEM);
    cudaFuncSetAttribute(edge_kernel, cudaFuncAttributeMaxDynamicSharedMemorySize, EDGE_SMEM);
    cudaFuncSetAttribute(node_kernel, cudaFuncAttributeMaxDynamicSharedMemorySize, NODE_SMEM);

    zero_kernel<<<(NN*HID/4 + 255)/256, 256>>>();
    pre_kernel <<<(NN + 63)/64, 256, PRE_SMEM>>>(h, We1);
    edge_kernel<<<NE/128, 256, EDGE_SMEM>>>(x, eidx, edge_attr,
                                            We1, be1, We2, be2, Winf, binf,
                                            Wx1, bx1, Wx2);
    node_kernel<<<(NN + 63)/64, 256, NODE_SMEM>>>(h, x, mask,
                                                  Wn1, bn1, Wn2, bn2, out);
}

// round 9
// speedup vs baseline: 5.0790x; 1.0953x over previous
#include <cuda_runtime.h>

#define NN   50000
#define NE   640000
#define HID  128
#define NG   20
#define EF   4
#define XOUT_OFF (NN*HID)

typedef unsigned long long u64;

// scratch
__device__ __align__(16) float g_mi[NN*HID];
__device__ __align__(16) float g_p [NN*HID];
__device__ __align__(16) float g_q [NN*HID];
__device__ __align__(16) float g_dx[NN*3];

__device__ __forceinline__ float sigmoidf_(float v){ return 1.f/(1.f+__expf(-v)); }
__device__ __forceinline__ float siluf_(float v){ return v/(1.f+__expf(-v)); }
__device__ __forceinline__ int clampi(int v){ return v < 0 ? 0 : (v >= NN ? NN-1 : v); }
__device__ __forceinline__ float4 ld4(const float* p){ return *(const float4*)p; }

__device__ __forceinline__ void red_add_v4(float* a, float x, float y, float z, float w){
    asm volatile("red.global.add.v4.f32 [%0], {%1,%2,%3,%4};"
                 :: "l"(a), "f"(x), "f"(y), "f"(z), "f"(w) : "memory");
}

#define PK2(d,lo,hi)  asm("mov.b64 %0, {%1,%2};" : "=l"(d) : "f"(lo), "f"(hi))
#define UPK2(lo,hi,s) asm("mov.b64 {%0,%1}, %2;" : "=f"(lo), "=f"(hi) : "l"(s))
#define FMA2(d,a,b)   asm("fma.rn.f32x2 %0, %1, %2, %0;" : "+l"(d) : "l"(a), "l"(b))

__device__ __forceinline__ unsigned smem_u32(const void* p){
    unsigned a;
    asm("{ .reg .u64 t; cvta.to.shared.u64 t, %1; cvt.u32.u64 %0, t; }" : "=r"(a) : "l"(p));
    return a;
}
__device__ __forceinline__ void lds2u64(u64& a, u64& b, unsigned addr){
    asm volatile("ld.shared.v2.u64 {%0,%1}, [%2];" : "=l"(a), "=l"(b) : "r"(addr));
}
__device__ __forceinline__ void sts_u64(unsigned addr, u64 v){
    asm volatile("st.shared.u64 [%0], %1;" :: "r"(addr), "l"(v));
}

__global__ void zero_kernel() {
    int i = blockIdx.x*256 + threadIdx.x;
    if (i < NN*HID/4) ((float4*)g_mi)[i] = make_float4(0.f,0.f,0.f,0.f);
    if (i < NN*3/4)   ((float4*)g_dx)[i] = make_float4(0.f,0.f,0.f,0.f);
}

// ---------------- shared FFMA2 mainloop (8 rows x 8 cols per thread) -------
// A in smem: col-major, LD4 f4-units per col row-slab; row pairs via v2.u64.
template<int KC, int LD4, bool SWZ>
__device__ __forceinline__ void gemm_main(unsigned asu, const float4* __restrict__ ws4,
                                          int tx, int ty, u64 acc[4][8], int kbase)
{
    #pragma unroll 8
    for (int kk = 0; kk < KC; ++kk) {
        int k = kbase + kk;
        int swz = SWZ ? ((k>>3)&7) : 0;
        u64 a01,a23,a45,a67;
        lds2u64(a01,a23, asu + (unsigned)(k*LD4 + ((2*ty)  ^swz))*16u);
        lds2u64(a45,a67, asu + (unsigned)(k*LD4 + ((2*ty+1)^swz))*16u);
        float4 w0 = ws4[kk*32 + 2*tx], w1 = ws4[kk*32 + 2*tx + 1];
        float wv[8] = {w0.x,w0.y,w0.z,w0.w,w1.x,w1.y,w1.z,w1.w};
        u64 wp[8];
        #pragma unroll
        for (int j=0;j<8;j++) PK2(wp[j], wv[j], wv[j]);
        #pragma unroll
        for (int j=0;j<8;j++){
            FMA2(acc[0][j], a01, wp[j]);
            FMA2(acc[1][j], a23, wp[j]);
            FMA2(acc[2][j], a45, wp[j]);
            FMA2(acc[3][j], a67, wp[j]);
        }
    }
}
__device__ __forceinline__ void zacc4x8(u64 acc[4][8]){
    #pragma unroll
    for (int p=0;p<4;p++)
        #pragma unroll
        for (int j=0;j<8;j++) acc[p][j]=0ull;
}
template<int NF, int NT>
__device__ __forceinline__ void stage_ld(float4 w[NF], const float* Wg, int kb, int t){
    const float4* Wg4 = (const float4*)(Wg + kb*128);
    #pragma unroll
    for (int i=0;i<NF;i++) w[i] = Wg4[t + NT*i];
}
template<int NF, int NT>
__device__ __forceinline__ void stage_st(float4* ws4, const float4 w[NF], int t){
    #pragma unroll
    for (int i=0;i<NF;i++) ws4[t + NT*i] = w[i];
}
// transposed store of rowpair p for column k (LD4-stride buffer, swizzled)
template<int LD4>
__device__ __forceinline__ unsigned colk_addr(unsigned su, int k, int ty, int p){
    int swz = (k>>3)&7;
    return su + (unsigned)(k*LD4 + ((2*ty + (p>>1)) ^ swz))*16u + (unsigned)(p&1)*8u;
}

// ---------------- pre: P = h@We1[0:128], Q = h@We1[128:256] ----------------
// 128 threads, 64 nodes/CTA. hs [128 k][17 f4] + ws [32][128]
#define PRE_SMEM ((128*68 + 32*128)*4)
__global__ __launch_bounds__(128,4) void pre_kernel(
    const float* __restrict__ h, const float* __restrict__ We1)
{
    extern __shared__ float sm[];
    float*  hs  = sm;
    float4* ws4 = (float4*)(sm + 128*68);
    const int t = threadIdx.x;
    const int tx = t & 15, ty = t >> 4;      // ty 0..7
    const int c0 = 8*tx, r0 = 8*ty;
    const int n0 = blockIdx.x * 64;
    const unsigned su = smem_u32(sm);

    for (int i = t; i < 64*128; i += 128) {
        int e = i >> 7, k = i & 127;
        int node = n0 + e;
        hs[k*68 + e] = (node < NN) ? h[node*HID + k] : 0.f;
    }

    u64 acc[4][8];
    float lo[8], hi[8];
    float4 wa[8];
    stage_ld<8,128>(wa, We1, 0, t);

    #pragma unroll
    for (int g=0; g<2; g++) {
        const float* Wg = g ? (We1 + 128*128) : We1;
        float* dst = g ? g_q : g_p;
        zacc4x8(acc);
        #pragma unroll
        for (int s=0; s<4; s++) {
            __syncthreads();
            stage_st<8,128>(ws4, wa, t);
            if (s < 3)      stage_ld<8,128>(wa, Wg, 32*(s+1), t);
            else if (g==0)  stage_ld<8,128>(wa, We1 + 128*128, 0, t);
            __syncthreads();
            gemm_main<32,17,false>(su, ws4, tx, ty, acc, 32*s);
        }
        #pragma unroll
        for (int p=0;p<4;p++) {
            #pragma unroll
            for (int j=0;j<8;j++) UPK2(lo[j], hi[j], acc[p][j]);
            int nA = n0 + r0 + 2*p, nB = nA + 1;
            if (nA < NN) {
                *(float4*)(dst + nA*HID + c0)   = make_float4(lo[0],lo[1],lo[2],lo[3]);
                *(float4*)(dst + nA*HID + c0+4) = make_float4(lo[4],lo[5],lo[6],lo[7]);
            }
            if (nB < NN) {
                *(float4*)(dst + nB*HID + c0)   = make_float4(hi[0],hi[1],hi[2],hi[3]);
                *(float4*)(dst + nB*HID + c0+4) = make_float4(hi[4],hi[5],hi[6],hi[7]);
            }
        }
    }
}

// ---------------- edge kernel: 128 edges/CTA, double-buffered staging ------
// t1s [128 cols][33 f4] @0 (16896 floats) | ws [64][128] @16896 (8192 floats)
#define EDGE_SMEM ((16896 + 8192)*4)
__global__ __launch_bounds__(256,2) void edge_kernel(
    const float* __restrict__ x,
    const int* __restrict__ eidx, const float* __restrict__ edge_attr,
    const float* __restrict__ We1, const float* __restrict__ be1,
    const float* __restrict__ We2, const float* __restrict__ be2,
    const float* __restrict__ Winf, const float* __restrict__ binf,
    const float* __restrict__ Wx1, const float* __restrict__ bx1,
    const float* __restrict__ Wx2)
{
    extern __shared__ float sm[];
    float*  fe   = sm;                       // [24][132] aliases t1s
    float4* ws4  = (float4*)(sm + 16896);
    __shared__ int   dstl[128], srcl[128];
    __shared__ float rels[3][128], dsv[128];
    __shared__ float be1s[128], be2s[128], bx1s[128], winfs[128], wx2s[128];

    const int t  = threadIdx.x;
    const int tx = t & 15, ty = t >> 4;
    const int c0 = 8*tx, r0 = 8*ty;
    const long e0 = (long)blockIdx.x * 128;
    const unsigned t1su = smem_u32(sm);

    float4 w1[3], w2[8];
    stage_ld<3,256>(w1, We1 + 256*128, 0, t);

    if (t < 128) {
        int s = clampi(eidx[e0 + t]);
        int d = clampi(eidx[NE + e0 + t]);
        srcl[t] = s; dstl[t] = d;
        float d0 = x[d*3+0]-x[s*3+0];
        float d1 = x[d*3+1]-x[s*3+1];
        float d2 = x[d*3+2]-x[s*3+2];
        rels[0][t]=d0; rels[1][t]=d1; rels[2][t]=d2;
        dsv[t] = sqrtf(d0*d0 + d1*d1 + d2*d2 + 1e-8f);
        be1s[t]=be1[t]; be2s[t]=be2[t]; bx1s[t]=bx1[t];
        winfs[t]=Winf[t]; wx2s[t]=Wx2[t];
    }
    __syncthreads();

    // feature tile fe[24][132]: gauss(d)[20] | edge_attr[4]
    const float step  = 10.f/19.f;
    const float coeff = -0.5f/(step*step);
    for (int i = t; i < 24*128; i += 256) {
        int e = i & 127, k = i >> 7;
        float v;
        if (k < NG) { float dd = dsv[e] - step*(float)k; v = __expf(coeff*dd*dd); }
        else        { v = edge_attr[(e0+e)*EF + (k-NG)]; }
        fe[k*132 + e] = v;
    }
    stage_st<3,256>(ws4, w1, t);
    stage_ld<8,256>(w2, We2, 0, t);          // prefetch GEMM2 s0
    __syncthreads();

    u64 acc[4][8];
    float lo[8], hi[8];

    // ---- GEMM1 (K=24) ----
    zacc4x8(acc);
    gemm_main<24,33,false>(t1su, ws4, tx, ty, acc, 0);
    __syncthreads();                          // ws + fe free
    stage_st<8,256>(ws4, w2, t);
    stage_ld<8,256>(w2, We2, 64, t);          // prefetch GEMM2 s1

    // epilogue1: + P[dst] + Q[src] + be1 -> silu -> t1s (transposed, swizzled)
    #pragma unroll
    for (int p=0;p<4;p++) {
        #pragma unroll
        for (int j=0;j<8;j++) UPK2(lo[j], hi[j], acc[p][j]);
        int mA = r0 + 2*p, mB = mA + 1;
        {
            int dn = dstl[mA], sn = srcl[mA];
            float4 p0 = ld4(g_p + dn*HID + c0), p1 = ld4(g_p + dn*HID + c0 + 4);
            float4 q0 = ld4(g_q + sn*HID + c0), q1 = ld4(g_q + sn*HID + c0 + 4);
            lo[0]=siluf_(lo[0]+p0.x+q0.x+be1s[c0+0]); lo[1]=siluf_(lo[1]+p0.y+q0.y+be1s[c0+1]);
            lo[2]=siluf_(lo[2]+p0.z+q0.z+be1s[c0+2]); lo[3]=siluf_(lo[3]+p0.w+q0.w+be1s[c0+3]);
            lo[4]=siluf_(lo[4]+p1.x+q1.x+be1s[c0+4]); lo[5]=siluf_(lo[5]+p1.y+q1.y+be1s[c0+5]);
            lo[6]=siluf_(lo[6]+p1.z+q1.z+be1s[c0+6]); lo[7]=siluf_(lo[7]+p1.w+q1.w+be1s[c0+7]);
        }
        {
            int dn = dstl[mB], sn = srcl[mB];
            float4 p0 = ld4(g_p + dn*HID + c0), p1 = ld4(g_p + dn*HID + c0 + 4);
            float4 q0 = ld4(g_q + sn*HID + c0), q1 = ld4(g_q + sn*HID + c0 + 4);
            hi[0]=siluf_(hi[0]+p0.x+q0.x+be1s[c0+0]); hi[1]=siluf_(hi[1]+p0.y+q0.y+be1s[c0+1]);
            hi[2]=siluf_(hi[2]+p0.z+q0.z+be1s[c0+2]); hi[3]=siluf_(hi[3]+p0.w+q0.w+be1s[c0+3]);
            hi[4]=siluf_(hi[4]+p1.x+q1.x+be1s[c0+4]); hi[5]=siluf_(hi[5]+p1.y+q1.y+be1s[c0+5]);
            hi[6]=siluf_(hi[6]+p1.z+q1.z+be1s[c0+6]); hi[7]=siluf_(hi[7]+p1.w+q1.w+be1s[c0+7]);
        }
        #pragma unroll
        for (int j=0;j<8;j++) {
            u64 v; PK2(v, lo[j], hi[j]);
            sts_u64(colk_addr<33>(t1su, c0+j, ty, p), v);
        }
    }
    __syncthreads();                          // t1s + ws(We2 s0) ready

    // ---- GEMM2 ----
    zacc4x8(acc);
    gemm_main<64,33,true>(t1su, ws4, tx, ty, acc, 0);
    __syncthreads();
    stage_st<8,256>(ws4, w2, t);
    stage_ld<8,256>(w2, Wx1, 0, t);           // prefetch GEMM3 s0
    __syncthreads();
    gemm_main<64,33,true>(t1su, ws4, tx, ty, acc, 64);
    __syncthreads();                          // all t1s reads + ws free
    stage_st<8,256>(ws4, w2, t);
    stage_ld<8,256>(w2, Wx1, 64, t);          // prefetch GEMM3 s1

    // epilogue2: silu, eij, scatter, rewrite t1s with mij
    {
        float bi = binf[0];
        #pragma unroll
        for (int p=0;p<4;p++) {
            #pragma unroll
            for (int j=0;j<8;j++) UPK2(lo[j], hi[j], acc[p][j]);
            #pragma unroll
            for (int j=0;j<8;j++) {
                lo[j] = siluf_(lo[j] + be2s[c0+j]);
                hi[j] = siluf_(hi[j] + be2s[c0+j]);
            }
            float sA = 0.f, sB = 0.f;
            #pragma unroll
            for (int j=0;j<8;j++) { sA += lo[j]*winfs[c0+j]; sB += hi[j]*winfs[c0+j]; }
            #pragma unroll
            for (int off=8; off; off >>= 1) {
                sA += __shfl_xor_sync(0xffffffffu, sA, off);
                sB += __shfl_xor_sync(0xffffffffu, sB, off);
            }
            int mA = r0 + 2*p, mB = mA + 1;
            float egA = sigmoidf_(sA + bi), egB = sigmoidf_(sB + bi);
            int dnA = dstl[mA], dnB = dstl[mB];
            red_add_v4(&g_mi[dnA*HID + c0],     lo[0]*egA, lo[1]*egA, lo[2]*egA, lo[3]*egA);
            red_add_v4(&g_mi[dnA*HID + c0 + 4], lo[4]*egA, lo[5]*egA, lo[6]*egA, lo[7]*egA);
            red_add_v4(&g_mi[dnB*HID + c0],     hi[0]*egB, hi[1]*egB, hi[2]*egB, hi[3]*egB);
            red_add_v4(&g_mi[dnB*HID + c0 + 4], hi[4]*egB, hi[5]*egB, hi[6]*egB, hi[7]*egB);
            #pragma unroll
            for (int j=0;j<8;j++) {
                u64 v; PK2(v, lo[j], hi[j]);
                sts_u64(colk_addr<33>(t1su, c0+j, ty, p), v);
            }
        }
    }
    __syncthreads();                          // t1s(mij) + ws(Wx1 s0) ready

    // ---- GEMM3 ----
    zacc4x8(acc);
    gemm_main<64,33,true>(t1su, ws4, tx, ty, acc, 0);
    __syncthreads();
    stage_st<8,256>(ws4, w2, t);
    __syncthreads();
    gemm_main<64,33,true>(t1su, ws4, tx, ty, acc, 64);

    // epilogue3: xg = tanh(silu(.)·Wx2); coord scatter
    #pragma unroll
    for (int p=0;p<4;p++) {
        #pragma unroll
        for (int j=0;j<8;j++) UPK2(lo[j], hi[j], acc[p][j]);
        float qA = 0.f, qB = 0.f;
        #pragma unroll
        for (int j=0;j<8;j++) {
            float b = bx1s[c0+j], w = wx2s[c0+j];
            qA += siluf_(lo[j] + b)*w;
            qB += siluf_(hi[j] + b)*w;
        }
        #pragma unroll
        for (int off=8; off; off >>= 1) {
            qA += __shfl_xor_sync(0xffffffffu, qA, off);
            qB += __shfl_xor_sync(0xffffffffu, qB, off);
        }
        if (tx < 3) {
            int mA = r0 + 2*p, mB = mA + 1;
            float sA = tanhf(qA) / (dsv[mA] + 1.f);
            float sB = tanhf(qB) / (dsv[mB] + 1.f);
            atomicAdd(&g_dx[dstl[mA]*3 + tx], rels[tx][mA]*sA);
            atomicAdd(&g_dx[dstl[mB]*3 + tx], rels[tx][mB]*sB);
        }
    }
}

// ---------------- node kernel: 128 threads, 64 nodes/CTA -------------------
// zs [256 k][17 f4] @0 (17408 floats) | ws [32][128] @17408 (4096 floats)
#define NODE_SMEM ((17408 + 4096)*4)
__global__ __launch_bounds__(128,2) void node_kernel(
    const float* __restrict__ h, const float* __restrict__ x,
    const float* __restrict__ mask,
    const float* __restrict__ Wn1, const float* __restrict__ bn1,
    const float* __restrict__ Wn2, const float* __restrict__ bn2,
    float* __restrict__ out)
{
    extern __shared__ float sm[];
    float*  zs  = sm;
    float4* ws4 = (float4*)(sm + 17408);
    const unsigned su = smem_u32(sm);

    const int t  = threadIdx.x;
    const int tx = t & 15, ty = t >> 4;      // ty 0..7
    const int c0 = 8*tx, r0 = 8*ty;
    const int n0 = blockIdx.x * 64;

    for (int i = t; i < 64*256; i += 128) {
        int e = i >> 8, k = i & 255;
        int node = n0 + e;
        float v = 0.f;
        if (node < NN)
            v = (k < HID) ? g_mi[node*HID + k] : h[node*HID + (k-HID)];
        zs[k*68 + e] = v;
    }

    u64 acc[4][8];
    float lo[8], hi[8];
    float4 wa[8];
    stage_ld<8,128>(wa, Wn1, 0, t);

    // ---- GEMM1: K=256, 8 stages ----
    zacc4x8(acc);
    #pragma unroll
    for (int s=0; s<8; s++) {
        __syncthreads();                       // s=0 also guards zs fill
        stage_st<8,128>(ws4, wa, t);
        if (s < 7) stage_ld<8,128>(wa, Wn1, 32*(s+1), t);
        else       stage_ld<8,128>(wa, Wn2, 0, t);
        __syncthreads();
        gemm_main<32,17,false>(su, ws4, tx, ty, acc, 32*s);
    }
    __syncthreads();                           // ws free + all zs reads done
    stage_st<8,128>(ws4, wa, t);
    stage_ld<8,128>(wa, Wn2, 32, t);

    // epilogue1: silu -> rewrite zs cols 0..127 as t1 (swizzled)
    #pragma unroll
    for (int p=0;p<4;p++) {
        #pragma unroll
        for (int j=0;j<8;j++) UPK2(lo[j], hi[j], acc[p][j]);
        #pragma unroll
        for (int j=0;j<8;j++) {
            float b = bn1[c0+j];
            lo[j] = siluf_(lo[j] + b);
            hi[j] = siluf_(hi[j] + b);
        }
        #pragma unroll
        for (int j=0;j<8;j++) {
            u64 v; PK2(v, lo[j], hi[j]);
            sts_u64(colk_addr<17>(su, c0+j, ty, p), v);
        }
    }
    __syncthreads();                           // t1 + ws(Wn2 s0) ready

    // ---- GEMM2: K=128, 4 stages ----
    zacc4x8(acc);
    #pragma unroll
    for (int s=0; s<4; s++) {
        gemm_main<32,17,true>(su, ws4, tx, ty, acc, 32*s);
        if (s < 3) {
            __syncthreads();
            stage_st<8,128>(ws4, wa, t);
            if (s < 2) stage_ld<8,128>(wa, Wn2, 32*(s+2), t);
            __syncthreads();
        }
    }

    #pragma unroll
    for (int p=0;p<4;p++) {
        #pragma unroll
        for (int j=0;j<8;j++) UPK2(lo[j], hi[j], acc[p][j]);
        int nA = n0 + r0 + 2*p, nB = nA + 1;
        if (nA < NN) {
            float4 h0 = ld4(h + nA*HID + c0), h1 = ld4(h + nA*HID + c0 + 4);
            *(float4*)(out + nA*HID + c0) = make_float4(
                h0.x+lo[0]+bn2[c0+0], h0.y+lo[1]+bn2[c0+1],
                h0.z+lo[2]+bn2[c0+2], h0.w+lo[3]+bn2[c0+3]);
            *(float4*)(out + nA*HID + c0 + 4) = make_float4(
                h1.x+lo[4]+bn2[c0+4], h1.y+lo[5]+bn2[c0+5],
                h1.z+lo[6]+bn2[c0+6], h1.w+lo[7]+bn2[c0+7]);
        }
        if (nB < NN) {
            float4 h0 = ld4(h + nB*HID + c0), h1 = ld4(h + nB*HID + c0 + 4);
            *(float4*)(out + nB*HID + c0) = make_float4(
                h0.x+hi[0]+bn2[c0+0], h0.y+hi[1]+bn2[c0+1],
                h0.z+hi[2]+bn2[c0+2], h0.w+hi[3]+bn2[c0+3]);
            *(float4*)(out + nB*HID + c0 + 4) = make_float4(
                h1.x+hi[4]+bn2[c0+4], h1.y+hi[5]+bn2[c0+5],
                h1.z+hi[6]+bn2[c0+6], h1.w+hi[7]+bn2[c0+7]);
        }
    }
    for (int i = t; i < 64*3; i += 128) {
        int e = i/3, a = i - 3*e;
        int node = n0 + e;
        if (node < NN)
            out[XOUT_OFF + node*3 + a] = x[node*3 + a] + g_dx[node*3 + a]*mask[node];
    }
}

extern "C" void kernel_launch(void* const* d_in, const int* in_sizes, int n_in,
                              void* d_out, int out_size)
{
    const float* h         = (const float*)d_in[0];
    const float* x         = (const float*)d_in[1];
    const int*   eidx      = (const int*)d_in[2];   // int32 (jax x64 disabled)
    const float* mask      = (const float*)d_in[3];
    const float* edge_attr = (const float*)d_in[4];
    const float* We1  = (const float*)d_in[5];
    const float* be1  = (const float*)d_in[6];
    const float* We2  = (const float*)d_in[7];
    const float* be2  = (const float*)d_in[8];
    const float* Winf = (const float*)d_in[9];
    const float* binf = (const float*)d_in[10];
    const float* Wx1  = (const float*)d_in[11];
    const float* bx1  = (const float*)d_in[12];
    const float* Wx2  = (const float*)d_in[13];
    const float* Wn1  = (const float*)d_in[14];
    const float* bn1  = (const float*)d_in[15];
    const float* Wn2  = (const float*)d_in[16];
    const float* bn2  = (const float*)d_in[17];
    float* out = (float*)d_out;

    cudaFuncSetAttribute(pre_kernel,  cudaFuncAttributeMaxDynamicSharedMemorySize, PRE_SMEM);
    cudaFuncSetAttribute(edge_kernel, cudaFuncAttributeMaxDynamicSharedMemorySize, EDGE_SMEM);
    cudaFuncSetAttribute(node_kernel, cudaFuncAttributeMaxDynamicSharedMemorySize, NODE_SMEM);

    zero_kernel<<<(NN*HID/4 + 255)/256, 256>>>();
    pre_kernel <<<(NN + 63)/64, 128, PRE_SMEM>>>(h, We1);
    edge_kernel<<<NE/128, 256, EDGE_SMEM>>>(x, eidx, edge_attr,
                                            We1, be1, We2, be2, Winf, binf,
                                            Wx1, bx1, Wx2);
    node_kernel<<<(NN + 63)/64, 128, NODE_SMEM>>>(h, x, mask,
                                                  Wn1, bn1, Wn2, bn2, out);
}